// round 6
// baseline (speedup 1.0000x reference)
#include <cuda_runtime.h>
#include <stdint.h>
#include <stddef.h>

#define NTOK 8192
#define EMB  1024
#define NH   16
#define HD   64

// ---------------- scratch (static device globals; no allocation) ----------------
__device__ float g_q[(size_t)NTOK * EMB];
__device__ float g_k[(size_t)NTOK * EMB];
__device__ float g_v[(size_t)NTOK * EMB];
__device__ float g_x[(size_t)NTOK * EMB];
__device__ float g_ln[(size_t)NTOK * EMB];

// ---------------- helpers ----------------
__device__ __forceinline__ float tf32f(float x) {
    unsigned u;
    asm("cvt.rna.tf32.f32 %0, %1;" : "=r"(u) : "f"(x));
    return __uint_as_float(u);
}
__device__ __forceinline__ unsigned tf32b(float x) {
    unsigned u;
    asm("cvt.rna.tf32.f32 %0, %1;" : "=r"(u) : "f"(x));
    return u;
}
__device__ __forceinline__ unsigned fbits(float x) { return __float_as_uint(x); }

__device__ __forceinline__ uint32_t smem_u32(const void* p) {
    uint32_t a;
    asm("{ .reg .u64 t; cvta.to.shared.u64 t, %1; cvt.u32.u64 %0, t; }" : "=r"(a) : "l"(p));
    return a;
}

__device__ __forceinline__ void cp16(uint32_t dst, const void* src) {
    asm volatile("cp.async.cg.shared.global [%0], [%1], 16;" :: "r"(dst), "l"(src));
}
#define CP_COMMIT() asm volatile("cp.async.commit_group;" ::: "memory")
#define CP_WAIT2()  asm volatile("cp.async.wait_group 2;" ::: "memory")

__device__ __forceinline__ void mma8(float c[4], const unsigned a[4], const unsigned b[2]) {
    asm volatile(
        "mma.sync.aligned.m16n8k8.row.col.f32.tf32.tf32.f32 "
        "{%0,%1,%2,%3},{%4,%5,%6,%7},{%8,%9},{%0,%1,%2,%3};\n"
        : "+f"(c[0]), "+f"(c[1]), "+f"(c[2]), "+f"(c[3])
        : "r"(a[0]), "r"(a[1]), "r"(a[2]), "r"(a[3]), "r"(b[0]), "r"(b[1]));
}

// ---------------- zero fill ----------------
__global__ void zero_kernel(float4* p) {
    p[(size_t)blockIdx.x * blockDim.x + threadIdx.x] = make_float4(0.f, 0.f, 0.f, 0.f);
}

// ============================================================================
// GEMM: C[M,N] = A[M,K] @ W[N,K]^T + bias
// CTA tile 128(M) x 256(N), 16 warps as 2(m) x 8(n), warp tile 64x32, KT=32.
// 4-stage cp.async pipeline. Frag-major SoA smem layout (identical to R4):
//   A pool: [kk(4)][slot(4)][mtG(8)][lane(32)] floats  (16 KB / stage)
//   B pool: [kk(4)][slot(2)][ntG(32)][lane(32)] floats (32 KB / stage)
// lane field swizzled: rb' = rb ^ tk, tk_A = (kk<<1)|(slot>>1), tk_B = (kk<<1)|slot.
// ============================================================================
#define GKT 32
#define STAGES 4
#define STAGE_FLOATS 12288               // 48 KB / 4
#define A_POOL_FLOATS 4096               // 16 KB
#define GEMM_SMEM_BYTES (STAGES * STAGE_FLOATS * 4)   // 192 KB

__global__ __launch_bounds__(512, 1) void gemm_mma_kernel(
    const float* __restrict__ A, const float* __restrict__ W,
    const float* __restrict__ bias, float* __restrict__ C,
    int M, int Nn, int K)
{
    extern __shared__ float smf[];
    const uint32_t sb = smem_u32(smf);
    const int tid  = threadIdx.x;
    const int lane = tid & 31;
    const int warp = tid >> 5;
    const int wm_i = warp & 1;        // 0..1  (m, 64 rows each)
    const int wn_i = warp >> 1;       // 0..7  (n, 32 cols each)
    const int bm = blockIdx.y * 128;
    const int bn = blockIdx.x * 256;

    const int T = K / GKT;            // 32

    // ---- stage issuer: 2 A-chunks + 4 B-chunks of 16B per thread (512 thr) ----
    auto issue_tile = [&](int t, int buf) {
        const uint32_t base = sb + (uint32_t)buf * (STAGE_FLOATS * 4);
        const float* Ap = A + (size_t)bm * K + t * GKT;
        const float* Wp = W + (size_t)bn * K + t * GKT;
#pragma unroll
        for (int i = 0; i < 2; i++) {
            int id = tid + i * 512;             // 0..1023
            int row = id >> 3;                  // 0..127
            int c4 = (id & 7) << 2;             // 0,4,...,28
            int kk = c4 >> 3;
            int s  = ((c4 & 4) >> 1) | ((row & 8) >> 3);
            int tk = (kk << 1) | ((c4 & 4) >> 2);
            int rb = (row & 7) ^ tk;
            uint32_t dst = base + (uint32_t)((((kk * 4 + s) * 8 + (row >> 4)) * 32 + (rb << 2)) * 4);
            cp16(dst, Ap + (size_t)row * K + c4);
        }
#pragma unroll
        for (int i = 0; i < 4; i++) {
            int id = tid + i * 512;             // 0..2047
            int row = id >> 3;                  // 0..255
            int c4 = (id & 7) << 2;
            int kk = c4 >> 3;
            int s  = (c4 & 4) >> 2;
            int tk = (kk << 1) | s;
            int rb = (row & 7) ^ tk;
            uint32_t dst = base + (uint32_t)((A_POOL_FLOATS +
                           (((kk * 2 + s) * 32 + (row >> 3)) * 32 + (rb << 2))) * 4);
            cp16(dst, Wp + (size_t)row * K + c4);
        }
        CP_COMMIT();
    };

    float acc[4][4][4];
#pragma unroll
    for (int mt = 0; mt < 4; mt++)
#pragma unroll
        for (int nt = 0; nt < 4; nt++)
#pragma unroll
            for (int i = 0; i < 4; i++) acc[mt][nt][i] = 0.f;

    // prologue: 3 stages in flight
    issue_tile(0, 0);
    issue_tile(1, 1);
    issue_tile(2, 2);

    const int l3 = lane & 3;
    const int lr = lane >> 2;   // 0..7

    for (int t = 0; t < T; t++) {
        CP_WAIT2();
        __syncthreads();
        if (t + 3 < T) issue_tile(t + 3, (t + 3) & 3);
        else CP_COMMIT();   // keep group numbering consistent

        const float* base = smf + (size_t)(t & 3) * STAGE_FLOATS;
        const float* bbase = base + A_POOL_FLOATS;

#pragma unroll
        for (int kk = 0; kk < 4; kk++) {
            unsigned af[4][4];
#pragma unroll
            for (int mt = 0; mt < 4; mt++) {
                int mtG = wm_i * 4 + mt;
#pragma unroll
                for (int s = 0; s < 4; s++) {
                    int tk = (kk << 1) | (s >> 1);
                    int li = ((lr ^ tk) << 2) | l3;
                    af[mt][s] = tf32b(base[((kk * 4 + s) * 8 + mtG) * 32 + li]);
                }
            }
            unsigned bf[4][2];
#pragma unroll
            for (int nt = 0; nt < 4; nt++) {
                int ntG = wn_i * 4 + nt;
#pragma unroll
                for (int s = 0; s < 2; s++) {
                    int tk = (kk << 1) | s;
                    int li = ((lr ^ tk) << 2) | l3;
                    bf[nt][s] = tf32b(bbase[((kk * 2 + s) * 32 + ntG) * 32 + li]);
                }
            }
#pragma unroll
            for (int mt = 0; mt < 4; mt++)
#pragma unroll
                for (int nt = 0; nt < 4; nt++)
                    mma8(acc[mt][nt], af[mt], bf[nt]);
        }
    }

    // ---- epilogue: bias + store ----
#pragma unroll
    for (int mt = 0; mt < 4; mt++) {
        int r0 = bm + wm_i * 64 + mt * 16 + lr;
#pragma unroll
        for (int nt = 0; nt < 4; nt++) {
            int c = bn + wn_i * 32 + nt * 8 + l3 * 2;
            float b0 = __ldg(bias + c), b1 = __ldg(bias + c + 1);
            *(float2*)(C + (size_t)r0 * Nn + c) =
                make_float2(acc[mt][nt][0] + b0, acc[mt][nt][1] + b1);
            *(float2*)(C + (size_t)(r0 + 8) * Nn + c) =
                make_float2(acc[mt][nt][2] + b0, acc[mt][nt][3] + b1);
        }
    }
}

// ---------------- attention (R1, passing) ----------------
#define QP 68
#define KP 68
#define VP 72
#define SP 132
#define ATTN_SMEM_BYTES ((128*QP + 128*KP + 128*VP + 128*SP + 3*128) * 4)

__global__ __launch_bounds__(256) void attn_kernel() {
    extern __shared__ float sm[];
    float* Qs   = sm;
    float* Ks   = Qs + 128 * QP;
    float* Vs   = Ks + 128 * KP;
    float* Ss   = Vs + 128 * VP;
    float* rowm = Ss + 128 * SP;
    float* rowl = rowm + 128;
    float* rowa = rowl + 128;

    const int p = blockIdx.y;
    int rate, off, head, segbase;
    if (p < 24)      { rate = 1; off = 0; segbase = (p / 6) * 2048;         head = p % 6; }
    else if (p < 34) { int q = p - 24; rate = 2; off = 1; segbase = (q / 5) * 4096; head = 6 + q % 5; }
    else             { int q = p - 34; rate = 4; off = 2; segbase = 0;             head = 11 + q; }

    const int tid = threadIdx.x;
    const int lane = tid & 31;
    const int warp = tid >> 5;
    const int q0 = blockIdx.x * 128;
    const float scale = 0.125f;

    for (int i = tid; i < 2048; i += 256) {
        int s = i >> 4;
        int c4 = (i & 15) << 2;
        int tok = segbase + off + (q0 + s) * rate;
        const float4 v = *(const float4*)(g_q + ((size_t)tok * NH + head) * HD + c4);
        float* d = Qs + s * QP + c4;
        d[0] = tf32f(v.x * scale); d[1] = tf32f(v.y * scale);
        d[2] = tf32f(v.z * scale); d[3] = tf32f(v.w * scale);
    }
    if (tid < 128) { rowm[tid] = -1e30f; rowl[tid] = 0.f; }
    __syncthreads();

    unsigned qf[8][4];
    {
        int r = warp * 16 + (lane >> 2);
#pragma unroll
        for (int kk = 0; kk < 8; kk++) {
            int c = kk * 8 + (lane & 3);
            qf[kk][0] = fbits(Qs[r * QP + c]);
            qf[kk][1] = fbits(Qs[(r + 8) * QP + c]);
            qf[kk][2] = fbits(Qs[r * QP + c + 4]);
            qf[kk][3] = fbits(Qs[(r + 8) * QP + c + 4]);
        }
    }
    float o[8][4];
#pragma unroll
    for (int nt = 0; nt < 8; nt++) { o[nt][0] = o[nt][1] = o[nt][2] = o[nt][3] = 0.f; }

    for (int j0 = 0; j0 < 2048; j0 += 128) {
        __syncthreads();
        for (int i = tid; i < 2048; i += 256) {
            int s = i >> 4;
            int c4 = (i & 15) << 2;
            int tok = segbase + off + (j0 + s) * rate;
            size_t base = ((size_t)tok * NH + head) * HD + c4;
            float4 kv = *(const float4*)(g_k + base);
            float4 vv = *(const float4*)(g_v + base);
            float* dk = Ks + s * KP + c4;
            dk[0] = tf32f(kv.x); dk[1] = tf32f(kv.y); dk[2] = tf32f(kv.z); dk[3] = tf32f(kv.w);
            float* dv = Vs + s * VP + c4;
            dv[0] = tf32f(vv.x); dv[1] = tf32f(vv.y); dv[2] = tf32f(vv.z); dv[3] = tf32f(vv.w);
        }
        __syncthreads();

        {
            int r = warp * 16 + (lane >> 2);
            for (int nt = 0; nt < 16; nt++) {
                float sc4[4] = {0.f, 0.f, 0.f, 0.f};
                int n = nt * 8 + (lane >> 2);
#pragma unroll
                for (int kk = 0; kk < 8; kk++) {
                    unsigned b[2];
                    int c = kk * 8 + (lane & 3);
                    b[0] = fbits(Ks[n * KP + c]);
                    b[1] = fbits(Ks[n * KP + c + 4]);
                    mma8(sc4, qf[kk], b);
                }
                int cc = nt * 8 + ((lane & 3) << 1);
                *(float2*)(Ss + r * SP + cc)       = make_float2(sc4[0], sc4[1]);
                *(float2*)(Ss + (r + 8) * SP + cc) = make_float2(sc4[2], sc4[3]);
            }
        }
        __syncthreads();

        {
            int r = tid >> 1, half = tid & 1;
            float* srow = Ss + r * SP + half * 64;
            float mx = -1e30f;
#pragma unroll 8
            for (int c = 0; c < 64; c++) mx = fmaxf(mx, srow[c]);
            mx = fmaxf(mx, __shfl_xor_sync(0xffffffffu, mx, 1));
            float mold = rowm[r];
            float mnew = fmaxf(mold, mx);
            float sum = 0.f;
#pragma unroll 8
            for (int c = 0; c < 64; c++) {
                float e = __expf(srow[c] - mnew);
                sum += e;
                srow[c] = tf32f(e);
            }
            sum += __shfl_xor_sync(0xffffffffu, sum, 1);
            if (half == 0) {
                float alpha = __expf(mold - mnew);
                rowa[r] = alpha;
                rowl[r] = rowl[r] * alpha + sum;
                rowm[r] = mnew;
            }
        }
        __syncthreads();

        {
            int r = warp * 16 + (lane >> 2);
            float a0 = rowa[r], a1 = rowa[r + 8];
#pragma unroll
            for (int nt = 0; nt < 8; nt++) {
                o[nt][0] *= a0; o[nt][1] *= a0; o[nt][2] *= a1; o[nt][3] *= a1;
            }
            for (int kk = 0; kk < 16; kk++) {
                unsigned a[4];
                int c = kk * 8 + (lane & 3);
                a[0] = fbits(Ss[r * SP + c]);
                a[1] = fbits(Ss[(r + 8) * SP + c]);
                a[2] = fbits(Ss[r * SP + c + 4]);
                a[3] = fbits(Ss[(r + 8) * SP + c + 4]);
                int kr = kk * 8 + (lane & 3);
                int nn = (lane >> 2);
#pragma unroll
                for (int nt = 0; nt < 8; nt++) {
                    unsigned b[2];
                    b[0] = fbits(Vs[kr * VP + nt * 8 + nn]);
                    b[1] = fbits(Vs[(kr + 4) * VP + nt * 8 + nn]);
                    mma8(o[nt], a, b);
                }
            }
        }
    }

    {
        int r = warp * 16 + (lane >> 2);
        float inv0 = 1.f / rowl[r];
        float inv1 = 1.f / rowl[r + 8];
        int tok0 = segbase + off + (q0 + r) * rate;
        int tok1 = segbase + off + (q0 + r + 8) * rate;
#pragma unroll
        for (int nt = 0; nt < 8; nt++) {
            int c = nt * 8 + ((lane & 3) << 1);
            *(float2*)(g_x + ((size_t)tok0 * NH + head) * HD + c) =
                make_float2(o[nt][0] * inv0, o[nt][1] * inv0);
            *(float2*)(g_x + ((size_t)tok1 * NH + head) * HD + c) =
                make_float2(o[nt][2] * inv1, o[nt][3] * inv1);
        }
    }
}

// ---------------- LayerNorm ----------------
__global__ __launch_bounds__(256) void ln_kernel(
    const float* __restrict__ x_in, float* __restrict__ y_out,
    const float* __restrict__ gam, const float* __restrict__ bet)
{
    __shared__ float red[16];
    const int row = blockIdx.x;
    const int tid = threadIdx.x;
    const int c = tid * 4;
    const float4 xv = *(const float4*)(x_in + (size_t)row * EMB + c);
    float s = xv.x + xv.y + xv.z + xv.w;
    float s2 = xv.x * xv.x + xv.y * xv.y + xv.z * xv.z + xv.w * xv.w;
#pragma unroll
    for (int o = 16; o; o >>= 1) {
        s += __shfl_xor_sync(0xffffffffu, s, o);
        s2 += __shfl_xor_sync(0xffffffffu, s2, o);
    }
    if ((tid & 31) == 0) { red[tid >> 5] = s; red[8 + (tid >> 5)] = s2; }
    __syncthreads();
    if (tid < 32) {
        float a = (tid < 8) ? red[tid] : 0.f;
        float b = (tid < 8) ? red[8 + tid] : 0.f;
#pragma unroll
        for (int o = 4; o; o >>= 1) {
            a += __shfl_xor_sync(0xffffffffu, a, o);
            b += __shfl_xor_sync(0xffffffffu, b, o);
        }
        if (tid == 0) { red[0] = a; red[1] = b; }
    }
    __syncthreads();
    const float mu = red[0] * (1.f / EMB);
    const float var = red[1] * (1.f / EMB) - mu * mu;
    const float rs = rsqrtf(var + 1e-5f);
    const float4 gv = *(const float4*)(gam + c);
    const float4 bv = *(const float4*)(bet + c);
    float4 ov;
    ov.x = (xv.x - mu) * rs * gv.x + bv.x;
    ov.y = (xv.y - mu) * rs * gv.y + bv.y;
    ov.z = (xv.z - mu) * rs * gv.z + bv.z;
    ov.w = (xv.w - mu) * rs * gv.w + bv.w;
    *(float4*)(y_out + (size_t)row * EMB + c) = ov;
}

// ---------------- launch ----------------
extern "C" void kernel_launch(void* const* d_in, const int* in_sizes, int n_in,
                              void* d_out, int out_size)
{
    (void)in_sizes; (void)n_in; (void)out_size;
    const float* query = (const float*)d_in[0];
    const float* key   = (const float*)d_in[1];
    const float* value = (const float*)d_in[2];
    const float* Wq = (const float*)d_in[3];
    const float* bq = (const float*)d_in[4];
    const float* Wk = (const float*)d_in[5];
    const float* bk = (const float*)d_in[6];
    const float* Wv = (const float*)d_in[7];
    const float* bv = (const float*)d_in[8];
    const float* Wo = (const float*)d_in[9];
    const float* bo = (const float*)d_in[10];
    const float* ln_g = (const float*)d_in[11];
    const float* ln_b = (const float*)d_in[12];
    float* out = (float*)d_out;

    float *pq, *pk, *pv, *px, *pln;
    cudaGetSymbolAddress((void**)&pq, g_q);
    cudaGetSymbolAddress((void**)&pk, g_k);
    cudaGetSymbolAddress((void**)&pv, g_v);
    cudaGetSymbolAddress((void**)&px, g_x);
    cudaGetSymbolAddress((void**)&pln, g_ln);

    zero_kernel<<<(NTOK * EMB / 4) / 256, 256>>>((float4*)px);

    cudaFuncSetAttribute(gemm_mma_kernel, cudaFuncAttributeMaxDynamicSharedMemorySize,
                         GEMM_SMEM_BYTES);
    dim3 ggrid(EMB / 256, NTOK / 128);
    gemm_mma_kernel<<<ggrid, 512, GEMM_SMEM_BYTES>>>(query, Wq, bq, pq, NTOK, EMB, EMB);
    gemm_mma_kernel<<<ggrid, 512, GEMM_SMEM_BYTES>>>(key,   Wk, bk, pk, NTOK, EMB, EMB);
    gemm_mma_kernel<<<ggrid, 512, GEMM_SMEM_BYTES>>>(value, Wv, bv, pv, NTOK, EMB, EMB);

    cudaFuncSetAttribute(attn_kernel, cudaFuncAttributeMaxDynamicSharedMemorySize,
                         ATTN_SMEM_BYTES);
    attn_kernel<<<dim3(16, 39), 256, ATTN_SMEM_BYTES>>>();

    ln_kernel<<<NTOK, 256>>>(px, pln, ln_g, ln_b);

    gemm_mma_kernel<<<ggrid, 512, GEMM_SMEM_BYTES>>>(pln, Wo, bo, out, NTOK, EMB, EMB);
}

// round 7
// speedup vs baseline: 1.3548x; 1.3548x over previous
#include <cuda_runtime.h>
#include <stdint.h>
#include <stddef.h>

#define NTOK 8192
#define EMB  1024
#define NH   16
#define HD   64

// ---------------- scratch (static device globals; no allocation) ----------------
__device__ float g_q[(size_t)NTOK * EMB];
__device__ float g_k[(size_t)NTOK * EMB];
__device__ float g_v[(size_t)NTOK * EMB];
__device__ float g_x[(size_t)NTOK * EMB];
__device__ float g_ln[(size_t)NTOK * EMB];

// ---------------- helpers ----------------
__device__ __forceinline__ float tf32f(float x) {
    unsigned u;
    asm("cvt.rna.tf32.f32 %0, %1;" : "=r"(u) : "f"(x));
    return __uint_as_float(u);
}
__device__ __forceinline__ unsigned tf32r(unsigned x) {
    unsigned u;
    asm("cvt.rna.tf32.f32 %0, %1;" : "=r"(u) : "r"(x));
    return u;
}
__device__ __forceinline__ unsigned fbits(float x) { return __float_as_uint(x); }

__device__ __forceinline__ uint32_t smem_u32(const void* p) {
    uint32_t a;
    asm("{ .reg .u64 t; cvta.to.shared.u64 t, %1; cvt.u32.u64 %0, t; }" : "=r"(a) : "l"(p));
    return a;
}

__device__ __forceinline__ void cp16(uint32_t dst, const void* src) {
    asm volatile("cp.async.cg.shared.global [%0], [%1], 16;" :: "r"(dst), "l"(src));
}
#define CP_COMMIT() asm volatile("cp.async.commit_group;" ::: "memory")
#define CP_WAIT1()  asm volatile("cp.async.wait_group 1;" ::: "memory")

__device__ __forceinline__ void ldsm4(unsigned& r0, unsigned& r1, unsigned& r2, unsigned& r3,
                                      uint32_t addr) {
    asm volatile("ldmatrix.sync.aligned.m8n8.x4.shared.b16 {%0,%1,%2,%3}, [%4];"
                 : "=r"(r0), "=r"(r1), "=r"(r2), "=r"(r3) : "r"(addr));
}
__device__ __forceinline__ void ldsm2(unsigned& r0, unsigned& r1, uint32_t addr) {
    asm volatile("ldmatrix.sync.aligned.m8n8.x2.shared.b16 {%0,%1}, [%2];"
                 : "=r"(r0), "=r"(r1) : "r"(addr));
}

__device__ __forceinline__ void mma8(float c[4], const unsigned a[4], const unsigned b[2]) {
    asm volatile(
        "mma.sync.aligned.m16n8k8.row.col.f32.tf32.tf32.f32 "
        "{%0,%1,%2,%3},{%4,%5,%6,%7},{%8,%9},{%0,%1,%2,%3};\n"
        : "+f"(c[0]), "+f"(c[1]), "+f"(c[2]), "+f"(c[3])
        : "r"(a[0]), "r"(a[1]), "r"(a[2]), "r"(a[3]), "r"(b[0]), "r"(b[1]));
}

// ---------------- zero fill ----------------
__global__ void zero_kernel(float4* p) {
    p[(size_t)blockIdx.x * blockDim.x + threadIdx.x] = make_float4(0.f, 0.f, 0.f, 0.f);
}

// ============================================================================
// GEMM: C[M,N] = A[M,K] @ W[N,K]^T + bias
// CTA tile 128(M) x 128(N), 8 warps as 2(m) x 4(n), warp tile 64x32, KT=32.
// 3-stage cp.async pipeline, 2 CTAs/SM. Tiles stored row-major (128B rows)
// with XOR-16B swizzle; fragments loaded via ldmatrix (tf32 b32 quadrants
// map exactly onto m8n8.b16 matrices), cvt.rna to tf32 after load.
// ============================================================================
#define GKT 32
#define NSTG 3
#define STAGE_FLOATS (2 * 128 * GKT)          // A + B, 8192 floats = 32 KB
#define B_OFF_FLOATS (128 * GKT)              // 4096
#define GEMM_SMEM_BYTES (NSTG * STAGE_FLOATS * 4)   // 96 KB

__global__ __launch_bounds__(256, 2) void gemm_mma_kernel(
    const float* __restrict__ A, const float* __restrict__ W,
    const float* __restrict__ bias, float* __restrict__ C,
    int M, int Nn, int K)
{
    extern __shared__ float smf[];
    const uint32_t sb = smem_u32(smf);
    const int tid  = threadIdx.x;
    const int lane = tid & 31;
    const int warp = tid >> 5;
    const int wm_i = warp & 1;        // 0..1  (m, 64 rows)
    const int wn_i = warp >> 1;       // 0..3  (n, 32 cols)
    const int bm = blockIdx.y * 128;
    const int bn = blockIdx.x * 128;

    const int T = K / GKT;            // 32

    // ---- stage issuer: 4 A-chunks + 4 B-chunks of 16B per thread ----
    auto issue_tile = [&](int t, int buf) {
        const uint32_t base = sb + (uint32_t)buf * (STAGE_FLOATS * 4);
        const float* Ap = A + (size_t)bm * K + t * GKT;
        const float* Wp = W + (size_t)bn * K + t * GKT;
#pragma unroll
        for (int i = 0; i < 4; i++) {
            int id = tid + i * 256;             // 0..1023
            int row = id >> 3;                  // 0..127
            int c4 = (id & 7) << 2;             // 0,4,...,28
            uint32_t off = (uint32_t)(row * 128 + c4 * 4);
            off ^= (uint32_t)((row & 7) << 4);
            cp16(base + off, Ap + (size_t)row * K + c4);
        }
#pragma unroll
        for (int i = 0; i < 4; i++) {
            int id = tid + i * 256;
            int row = id >> 3;
            int c4 = (id & 7) << 2;
            uint32_t off = (uint32_t)(B_OFF_FLOATS * 4 + row * 128 + c4 * 4);
            off ^= (uint32_t)((row & 7) << 4);
            cp16(base + off, Wp + (size_t)row * K + c4);
        }
        CP_COMMIT();
    };

    float acc[4][4][4];
#pragma unroll
    for (int mt = 0; mt < 4; mt++)
#pragma unroll
        for (int nt = 0; nt < 4; nt++)
#pragma unroll
            for (int i = 0; i < 4; i++) acc[mt][nt][i] = 0.f;

    issue_tile(0, 0);
    issue_tile(1, 1);

    // ldmatrix lane-address components (constant per thread)
    const int a_rl = ((lane >> 3) & 1) * 8 + (lane & 7);   // row within 16-row tile
    const int a_cl = ((lane >> 4) & 1) * 4;                // b32 col offset (0 or 4)
    const int b_rl = lane & 7;                             // row within 8-row tile
    const int b_cl = ((lane >> 3) & 1) * 4;                // b32 col offset

    for (int t = 0; t < T; t++) {
        CP_WAIT1();
        __syncthreads();
        if (t + 2 < T) issue_tile(t + 2, (t + 2) % NSTG);
        else CP_COMMIT();   // keep group numbering consistent

        const uint32_t base  = sb + (uint32_t)(t % NSTG) * (STAGE_FLOATS * 4);
        const uint32_t bbase = base + B_OFF_FLOATS * 4;

#pragma unroll
        for (int kk = 0; kk < 4; kk++) {
            unsigned af[4][4];
#pragma unroll
            for (int mt = 0; mt < 4; mt++) {
                int r = (wm_i * 4 + mt) * 16 + a_rl;
                int cb = kk * 8 + a_cl;
                uint32_t off = (uint32_t)(r * 128 + cb * 4) ^ (uint32_t)((r & 7) << 4);
                ldsm4(af[mt][0], af[mt][1], af[mt][2], af[mt][3], base + off);
#pragma unroll
                for (int s = 0; s < 4; s++) af[mt][s] = tf32r(af[mt][s]);
            }
            unsigned bf[4][2];
#pragma unroll
            for (int nt = 0; nt < 4; nt++) {
                int n = (wn_i * 4 + nt) * 8 + b_rl;
                int cb = kk * 8 + b_cl;
                uint32_t off = (uint32_t)(n * 128 + cb * 4) ^ (uint32_t)((n & 7) << 4);
                ldsm2(bf[nt][0], bf[nt][1], bbase + off);
                bf[nt][0] = tf32r(bf[nt][0]);
                bf[nt][1] = tf32r(bf[nt][1]);
            }
#pragma unroll
            for (int mt = 0; mt < 4; mt++)
#pragma unroll
                for (int nt = 0; nt < 4; nt++)
                    mma8(acc[mt][nt], af[mt], bf[nt]);
        }
    }

    // ---- epilogue: bias + store ----
    const int l3 = lane & 3;
    const int lr = lane >> 2;
#pragma unroll
    for (int mt = 0; mt < 4; mt++) {
        int r0 = bm + wm_i * 64 + mt * 16 + lr;
#pragma unroll
        for (int nt = 0; nt < 4; nt++) {
            int c = bn + wn_i * 32 + nt * 8 + l3 * 2;
            float b0 = __ldg(bias + c), b1 = __ldg(bias + c + 1);
            *(float2*)(C + (size_t)r0 * Nn + c) =
                make_float2(acc[mt][nt][0] + b0, acc[mt][nt][1] + b1);
            *(float2*)(C + (size_t)(r0 + 8) * Nn + c) =
                make_float2(acc[mt][nt][2] + b0, acc[mt][nt][3] + b1);
        }
    }
}

// ---------------- attention (R1, passing — frozen this round) ----------------
#define QP 68
#define KP 68
#define VP 72
#define SP 132
#define ATTN_SMEM_BYTES ((128*QP + 128*KP + 128*VP + 128*SP + 3*128) * 4)

__global__ __launch_bounds__(256) void attn_kernel() {
    extern __shared__ float sm[];
    float* Qs   = sm;
    float* Ks   = Qs + 128 * QP;
    float* Vs   = Ks + 128 * KP;
    float* Ss   = Vs + 128 * VP;
    float* rowm = Ss + 128 * SP;
    float* rowl = rowm + 128;
    float* rowa = rowl + 128;

    const int p = blockIdx.y;
    int rate, off, head, segbase;
    if (p < 24)      { rate = 1; off = 0; segbase = (p / 6) * 2048;         head = p % 6; }
    else if (p < 34) { int q = p - 24; rate = 2; off = 1; segbase = (q / 5) * 4096; head = 6 + q % 5; }
    else             { int q = p - 34; rate = 4; off = 2; segbase = 0;             head = 11 + q; }

    const int tid = threadIdx.x;
    const int lane = tid & 31;
    const int warp = tid >> 5;
    const int q0 = blockIdx.x * 128;
    const float scale = 0.125f;

    for (int i = tid; i < 2048; i += 256) {
        int s = i >> 4;
        int c4 = (i & 15) << 2;
        int tok = segbase + off + (q0 + s) * rate;
        const float4 v = *(const float4*)(g_q + ((size_t)tok * NH + head) * HD + c4);
        float* d = Qs + s * QP + c4;
        d[0] = tf32f(v.x * scale); d[1] = tf32f(v.y * scale);
        d[2] = tf32f(v.z * scale); d[3] = tf32f(v.w * scale);
    }
    if (tid < 128) { rowm[tid] = -1e30f; rowl[tid] = 0.f; }
    __syncthreads();

    unsigned qf[8][4];
    {
        int r = warp * 16 + (lane >> 2);
#pragma unroll
        for (int kk = 0; kk < 8; kk++) {
            int c = kk * 8 + (lane & 3);
            qf[kk][0] = fbits(Qs[r * QP + c]);
            qf[kk][1] = fbits(Qs[(r + 8) * QP + c]);
            qf[kk][2] = fbits(Qs[r * QP + c + 4]);
            qf[kk][3] = fbits(Qs[(r + 8) * QP + c + 4]);
        }
    }
    float o[8][4];
#pragma unroll
    for (int nt = 0; nt < 8; nt++) { o[nt][0] = o[nt][1] = o[nt][2] = o[nt][3] = 0.f; }

    for (int j0 = 0; j0 < 2048; j0 += 128) {
        __syncthreads();
        for (int i = tid; i < 2048; i += 256) {
            int s = i >> 4;
            int c4 = (i & 15) << 2;
            int tok = segbase + off + (j0 + s) * rate;
            size_t base = ((size_t)tok * NH + head) * HD + c4;
            float4 kv = *(const float4*)(g_k + base);
            float4 vv = *(const float4*)(g_v + base);
            float* dk = Ks + s * KP + c4;
            dk[0] = tf32f(kv.x); dk[1] = tf32f(kv.y); dk[2] = tf32f(kv.z); dk[3] = tf32f(kv.w);
            float* dv = Vs + s * VP + c4;
            dv[0] = tf32f(vv.x); dv[1] = tf32f(vv.y); dv[2] = tf32f(vv.z); dv[3] = tf32f(vv.w);
        }
        __syncthreads();

        {
            int r = warp * 16 + (lane >> 2);
            for (int nt = 0; nt < 16; nt++) {
                float sc4[4] = {0.f, 0.f, 0.f, 0.f};
                int n = nt * 8 + (lane >> 2);
#pragma unroll
                for (int kk = 0; kk < 8; kk++) {
                    unsigned b[2];
                    int c = kk * 8 + (lane & 3);
                    b[0] = fbits(Ks[n * KP + c]);
                    b[1] = fbits(Ks[n * KP + c + 4]);
                    mma8(sc4, qf[kk], b);
                }
                int cc = nt * 8 + ((lane & 3) << 1);
                *(float2*)(Ss + r * SP + cc)       = make_float2(sc4[0], sc4[1]);
                *(float2*)(Ss + (r + 8) * SP + cc) = make_float2(sc4[2], sc4[3]);
            }
        }
        __syncthreads();

        {
            int r = tid >> 1, half = tid & 1;
            float* srow = Ss + r * SP + half * 64;
            float mx = -1e30f;
#pragma unroll 8
            for (int c = 0; c < 64; c++) mx = fmaxf(mx, srow[c]);
            mx = fmaxf(mx, __shfl_xor_sync(0xffffffffu, mx, 1));
            float mold = rowm[r];
            float mnew = fmaxf(mold, mx);
            float sum = 0.f;
#pragma unroll 8
            for (int c = 0; c < 64; c++) {
                float e = __expf(srow[c] - mnew);
                sum += e;
                srow[c] = tf32f(e);
            }
            sum += __shfl_xor_sync(0xffffffffu, sum, 1);
            if (half == 0) {
                float alpha = __expf(mold - mnew);
                rowa[r] = alpha;
                rowl[r] = rowl[r] * alpha + sum;
                rowm[r] = mnew;
            }
        }
        __syncthreads();

        {
            int r = warp * 16 + (lane >> 2);
            float a0 = rowa[r], a1 = rowa[r + 8];
#pragma unroll
            for (int nt = 0; nt < 8; nt++) {
                o[nt][0] *= a0; o[nt][1] *= a0; o[nt][2] *= a1; o[nt][3] *= a1;
            }
            for (int kk = 0; kk < 16; kk++) {
                unsigned a[4];
                int c = kk * 8 + (lane & 3);
                a[0] = fbits(Ss[r * SP + c]);
                a[1] = fbits(Ss[(r + 8) * SP + c]);
                a[2] = fbits(Ss[r * SP + c + 4]);
                a[3] = fbits(Ss[(r + 8) * SP + c + 4]);
                int kr = kk * 8 + (lane & 3);
                int nn = (lane >> 2);
#pragma unroll
                for (int nt = 0; nt < 8; nt++) {
                    unsigned b[2];
                    b[0] = fbits(Vs[kr * VP + nt * 8 + nn]);
                    b[1] = fbits(Vs[(kr + 4) * VP + nt * 8 + nn]);
                    mma8(o[nt], a, b);
                }
            }
        }
    }

    {
        int r = warp * 16 + (lane >> 2);
        float inv0 = 1.f / rowl[r];
        float inv1 = 1.f / rowl[r + 8];
        int tok0 = segbase + off + (q0 + r) * rate;
        int tok1 = segbase + off + (q0 + r + 8) * rate;
#pragma unroll
        for (int nt = 0; nt < 8; nt++) {
            int c = nt * 8 + ((lane & 3) << 1);
            *(float2*)(g_x + ((size_t)tok0 * NH + head) * HD + c) =
                make_float2(o[nt][0] * inv0, o[nt][1] * inv0);
            *(float2*)(g_x + ((size_t)tok1 * NH + head) * HD + c) =
                make_float2(o[nt][2] * inv1, o[nt][3] * inv1);
        }
    }
}

// ---------------- LayerNorm ----------------
__global__ __launch_bounds__(256) void ln_kernel(
    const float* __restrict__ x_in, float* __restrict__ y_out,
    const float* __restrict__ gam, const float* __restrict__ bet)
{
    __shared__ float red[16];
    const int row = blockIdx.x;
    const int tid = threadIdx.x;
    const int c = tid * 4;
    const float4 xv = *(const float4*)(x_in + (size_t)row * EMB + c);
    float s = xv.x + xv.y + xv.z + xv.w;
    float s2 = xv.x * xv.x + xv.y * xv.y + xv.z * xv.z + xv.w * xv.w;
#pragma unroll
    for (int o = 16; o; o >>= 1) {
        s += __shfl_xor_sync(0xffffffffu, s, o);
        s2 += __shfl_xor_sync(0xffffffffu, s2, o);
    }
    if ((tid & 31) == 0) { red[tid >> 5] = s; red[8 + (tid >> 5)] = s2; }
    __syncthreads();
    if (tid < 32) {
        float a = (tid < 8) ? red[tid] : 0.f;
        float b = (tid < 8) ? red[8 + tid] : 0.f;
#pragma unroll
        for (int o = 4; o; o >>= 1) {
            a += __shfl_xor_sync(0xffffffffu, a, o);
            b += __shfl_xor_sync(0xffffffffu, b, o);
        }
        if (tid == 0) { red[0] = a; red[1] = b; }
    }
    __syncthreads();
    const float mu = red[0] * (1.f / EMB);
    const float var = red[1] * (1.f / EMB) - mu * mu;
    const float rs = rsqrtf(var + 1e-5f);
    const float4 gv = *(const float4*)(gam + c);
    const float4 bv = *(const float4*)(bet + c);
    float4 ov;
    ov.x = (xv.x - mu) * rs * gv.x + bv.x;
    ov.y = (xv.y - mu) * rs * gv.y + bv.y;
    ov.z = (xv.z - mu) * rs * gv.z + bv.z;
    ov.w = (xv.w - mu) * rs * gv.w + bv.w;
    *(float4*)(y_out + (size_t)row * EMB + c) = ov;
}

// ---------------- launch ----------------
extern "C" void kernel_launch(void* const* d_in, const int* in_sizes, int n_in,
                              void* d_out, int out_size)
{
    (void)in_sizes; (void)n_in; (void)out_size;
    const float* query = (const float*)d_in[0];
    const float* key   = (const float*)d_in[1];
    const float* value = (const float*)d_in[2];
    const float* Wq = (const float*)d_in[3];
    const float* bq = (const float*)d_in[4];
    const float* Wk = (const float*)d_in[5];
    const float* bk = (const float*)d_in[6];
    const float* Wv = (const float*)d_in[7];
    const float* bv = (const float*)d_in[8];
    const float* Wo = (const float*)d_in[9];
    const float* bo = (const float*)d_in[10];
    const float* ln_g = (const float*)d_in[11];
    const float* ln_b = (const float*)d_in[12];
    float* out = (float*)d_out;

    float *pq, *pk, *pv, *px, *pln;
    cudaGetSymbolAddress((void**)&pq, g_q);
    cudaGetSymbolAddress((void**)&pk, g_k);
    cudaGetSymbolAddress((void**)&pv, g_v);
    cudaGetSymbolAddress((void**)&px, g_x);
    cudaGetSymbolAddress((void**)&pln, g_ln);

    zero_kernel<<<(NTOK * EMB / 4) / 256, 256>>>((float4*)px);

    cudaFuncSetAttribute(gemm_mma_kernel, cudaFuncAttributeMaxDynamicSharedMemorySize,
                         GEMM_SMEM_BYTES);
    dim3 ggrid(EMB / 128, NTOK / 128);
    gemm_mma_kernel<<<ggrid, 256, GEMM_SMEM_BYTES>>>(query, Wq, bq, pq, NTOK, EMB, EMB);
    gemm_mma_kernel<<<ggrid, 256, GEMM_SMEM_BYTES>>>(key,   Wk, bk, pk, NTOK, EMB, EMB);
    gemm_mma_kernel<<<ggrid, 256, GEMM_SMEM_BYTES>>>(value, Wv, bv, pv, NTOK, EMB, EMB);

    cudaFuncSetAttribute(attn_kernel, cudaFuncAttributeMaxDynamicSharedMemorySize,
                         ATTN_SMEM_BYTES);
    attn_kernel<<<dim3(16, 39), 256, ATTN_SMEM_BYTES>>>();

    ln_kernel<<<NTOK, 256>>>(px, pln, ln_g, ln_b);

    gemm_mma_kernel<<<ggrid, 256, GEMM_SMEM_BYTES>>>(pln, Wo, bo, out, NTOK, EMB, EMB);
}

// round 8
// speedup vs baseline: 1.6385x; 1.2095x over previous
#include <cuda_runtime.h>
#include <stdint.h>
#include <stddef.h>

#define NTOK 8192
#define EMB  1024
#define NH   16
#define HD   64

// ---------------- scratch (static device globals; no allocation) ----------------
__device__ float g_q[(size_t)NTOK * EMB];
__device__ float g_k[(size_t)NTOK * EMB];
__device__ float g_v[(size_t)NTOK * EMB];
__device__ float g_x[(size_t)NTOK * EMB];
__device__ float g_ln[(size_t)NTOK * EMB];

// ---------------- helpers ----------------
__device__ __forceinline__ float tf32f(float x) {
    unsigned u;
    asm("cvt.rna.tf32.f32 %0, %1;" : "=r"(u) : "f"(x));
    return __uint_as_float(u);
}
__device__ __forceinline__ unsigned tf32r(unsigned x) {
    unsigned u;
    asm("cvt.rna.tf32.f32 %0, %1;" : "=r"(u) : "r"(x));
    return u;
}
__device__ __forceinline__ unsigned fbits(float x) { return __float_as_uint(x); }

__device__ __forceinline__ uint32_t smem_u32(const void* p) {
    uint32_t a;
    asm("{ .reg .u64 t; cvta.to.shared.u64 t, %1; cvt.u32.u64 %0, t; }" : "=r"(a) : "l"(p));
    return a;
}

__device__ __forceinline__ void cp16(uint32_t dst, const void* src) {
    asm volatile("cp.async.cg.shared.global [%0], [%1], 16;" :: "r"(dst), "l"(src));
}
#define CP_COMMIT() asm volatile("cp.async.commit_group;" ::: "memory")
#define CP_WAIT1()  asm volatile("cp.async.wait_group 1;" ::: "memory")
#define CP_WAIT0()  asm volatile("cp.async.wait_group 0;" ::: "memory")

__device__ __forceinline__ void ldsm4(unsigned& r0, unsigned& r1, unsigned& r2, unsigned& r3,
                                      uint32_t addr) {
    asm volatile("ldmatrix.sync.aligned.m8n8.x4.shared.b16 {%0,%1,%2,%3}, [%4];"
                 : "=r"(r0), "=r"(r1), "=r"(r2), "=r"(r3) : "r"(addr));
}
__device__ __forceinline__ void ldsm2(unsigned& r0, unsigned& r1, uint32_t addr) {
    asm volatile("ldmatrix.sync.aligned.m8n8.x2.shared.b16 {%0,%1}, [%2];"
                 : "=r"(r0), "=r"(r1) : "r"(addr));
}

__device__ __forceinline__ void mma8(float c[4], const unsigned a[4], const unsigned b[2]) {
    asm volatile(
        "mma.sync.aligned.m16n8k8.row.col.f32.tf32.tf32.f32 "
        "{%0,%1,%2,%3},{%4,%5,%6,%7},{%8,%9},{%0,%1,%2,%3};\n"
        : "+f"(c[0]), "+f"(c[1]), "+f"(c[2]), "+f"(c[3])
        : "r"(a[0]), "r"(a[1]), "r"(a[2]), "r"(a[3]), "r"(b[0]), "r"(b[1]));
}

// ---------------- zero fill ----------------
__global__ void zero_kernel(float4* p) {
    p[(size_t)blockIdx.x * blockDim.x + threadIdx.x] = make_float4(0.f, 0.f, 0.f, 0.f);
}

// ============================================================================
// GEMM (R7, unchanged — 145us each)
// ============================================================================
#define GKT 32
#define NSTG 3
#define STAGE_FLOATS (2 * 128 * GKT)
#define B_OFF_FLOATS (128 * GKT)
#define GEMM_SMEM_BYTES (NSTG * STAGE_FLOATS * 4)

__global__ __launch_bounds__(256, 2) void gemm_mma_kernel(
    const float* __restrict__ A, const float* __restrict__ W,
    const float* __restrict__ bias, float* __restrict__ C,
    int M, int Nn, int K)
{
    extern __shared__ float smf[];
    const uint32_t sb = smem_u32(smf);
    const int tid  = threadIdx.x;
    const int lane = tid & 31;
    const int warp = tid >> 5;
    const int wm_i = warp & 1;
    const int wn_i = warp >> 1;
    const int bm = blockIdx.y * 128;
    const int bn = blockIdx.x * 128;

    const int T = K / GKT;

    auto issue_tile = [&](int t, int buf) {
        const uint32_t base = sb + (uint32_t)buf * (STAGE_FLOATS * 4);
        const float* Ap = A + (size_t)bm * K + t * GKT;
        const float* Wp = W + (size_t)bn * K + t * GKT;
#pragma unroll
        for (int i = 0; i < 4; i++) {
            int id = tid + i * 256;
            int row = id >> 3;
            int c4 = (id & 7) << 2;
            uint32_t off = (uint32_t)(row * 128 + c4 * 4);
            off ^= (uint32_t)((row & 7) << 4);
            cp16(base + off, Ap + (size_t)row * K + c4);
        }
#pragma unroll
        for (int i = 0; i < 4; i++) {
            int id = tid + i * 256;
            int row = id >> 3;
            int c4 = (id & 7) << 2;
            uint32_t off = (uint32_t)(B_OFF_FLOATS * 4 + row * 128 + c4 * 4);
            off ^= (uint32_t)((row & 7) << 4);
            cp16(base + off, Wp + (size_t)row * K + c4);
        }
        CP_COMMIT();
    };

    float acc[4][4][4];
#pragma unroll
    for (int mt = 0; mt < 4; mt++)
#pragma unroll
        for (int nt = 0; nt < 4; nt++)
#pragma unroll
            for (int i = 0; i < 4; i++) acc[mt][nt][i] = 0.f;

    issue_tile(0, 0);
    issue_tile(1, 1);

    const int a_rl = ((lane >> 3) & 1) * 8 + (lane & 7);
    const int a_cl = ((lane >> 4) & 1) * 4;
    const int b_rl = lane & 7;
    const int b_cl = ((lane >> 3) & 1) * 4;

    for (int t = 0; t < T; t++) {
        CP_WAIT1();
        __syncthreads();
        if (t + 2 < T) issue_tile(t + 2, (t + 2) % NSTG);
        else CP_COMMIT();

        const uint32_t base  = sb + (uint32_t)(t % NSTG) * (STAGE_FLOATS * 4);
        const uint32_t bbase = base + B_OFF_FLOATS * 4;

#pragma unroll
        for (int kk = 0; kk < 4; kk++) {
            unsigned af[4][4];
#pragma unroll
            for (int mt = 0; mt < 4; mt++) {
                int r = (wm_i * 4 + mt) * 16 + a_rl;
                int cb = kk * 8 + a_cl;
                uint32_t off = (uint32_t)(r * 128 + cb * 4) ^ (uint32_t)((r & 7) << 4);
                ldsm4(af[mt][0], af[mt][1], af[mt][2], af[mt][3], base + off);
#pragma unroll
                for (int s = 0; s < 4; s++) af[mt][s] = tf32r(af[mt][s]);
            }
            unsigned bf[4][2];
#pragma unroll
            for (int nt = 0; nt < 4; nt++) {
                int n = (wn_i * 4 + nt) * 8 + b_rl;
                int cb = kk * 8 + b_cl;
                uint32_t off = (uint32_t)(n * 128 + cb * 4) ^ (uint32_t)((n & 7) << 4);
                ldsm2(bf[nt][0], bf[nt][1], bbase + off);
                bf[nt][0] = tf32r(bf[nt][0]);
                bf[nt][1] = tf32r(bf[nt][1]);
            }
#pragma unroll
            for (int mt = 0; mt < 4; mt++)
#pragma unroll
                for (int nt = 0; nt < 4; nt++)
                    mma8(acc[mt][nt], af[mt], bf[nt]);
        }
    }

    const int l3 = lane & 3;
    const int lr = lane >> 2;
#pragma unroll
    for (int mt = 0; mt < 4; mt++) {
        int r0 = bm + wm_i * 64 + mt * 16 + lr;
#pragma unroll
        for (int nt = 0; nt < 4; nt++) {
            int c = bn + wn_i * 32 + nt * 8 + l3 * 2;
            float b0 = __ldg(bias + c), b1 = __ldg(bias + c + 1);
            *(float2*)(C + (size_t)r0 * Nn + c) =
                make_float2(acc[mt][nt][0] + b0, acc[mt][nt][1] + b1);
            *(float2*)(C + (size_t)(r0 + 8) * Nn + c) =
                make_float2(acc[mt][nt][2] + b0, acc[mt][nt][3] + b1);
        }
    }
}

// ============================================================================
// Attention (rewritten): register-resident S, in-warp softmax, ldmatrix Q/K,
// cp.async K/V staging, 2 CTAs/SM. 39 problems x 16 q-blocks; per warp 16 rows.
// ============================================================================
#define AQP 68
#define AKP 68
#define AVP 72
#define ATTN_SMEM_BYTES ((128*AQP + 128*AKP + 128*AVP) * 4)   // 104 KB

__global__ __launch_bounds__(256, 2) void attn_kernel() {
    extern __shared__ float sm[];
    float* Qs = sm;
    float* Vs = sm + 128 * AQP + 128 * AKP;
    const uint32_t sb  = smem_u32(sm);
    const uint32_t ksb = sb + 128 * AQP * 4;

    const int p = blockIdx.y;
    int rate, off, head, segbase;
    if (p < 24)      { rate = 1; off = 0; segbase = (p / 6) * 2048;         head = p % 6; }
    else if (p < 34) { int q = p - 24; rate = 2; off = 1; segbase = (q / 5) * 4096; head = 6 + q % 5; }
    else             { int q = p - 34; rate = 4; off = 2; segbase = 0;             head = 11 + q; }

    const int tid = threadIdx.x;
    const int lane = tid & 31;
    const int warp = tid >> 5;
    const int l3 = lane & 3;
    const int lr = lane >> 2;
    const int q0 = blockIdx.x * 128;
    const float scale = 0.125f;

    // ---- Q staging: scaled + tf32, pitch AQP ----
    for (int i = tid; i < 2048; i += 256) {
        int s = i >> 4;
        int c4 = (i & 15) << 2;
        int tok = segbase + off + (q0 + s) * rate;
        const float4 v = *(const float4*)(g_q + ((size_t)tok * NH + head) * HD + c4);
        float* d = Qs + s * AQP + c4;
        d[0] = tf32f(v.x * scale); d[1] = tf32f(v.y * scale);
        d[2] = tf32f(v.z * scale); d[3] = tf32f(v.w * scale);
    }

    // ldmatrix lane-address components
    const int a_rl = ((lane >> 3) & 1) * 8 + (lane & 7);
    const int a_cl = ((lane >> 4) & 1) * 4;
    const int b_rl = lane & 7;
    const int b_cl = ((lane >> 3) & 1) * 4;
    const int srcA = (lane & ~3) | (l3 >> 1);
    const int srcB = srcA + 2;
    const bool odd = (l3 & 1);

    float o[8][4];
#pragma unroll
    for (int nt = 0; nt < 8; nt++) { o[nt][0] = o[nt][1] = o[nt][2] = o[nt][3] = 0.f; }
    float m0 = -1e30f, m1 = -1e30f, l0 = 0.f, l1 = 0.f;

    for (int j0 = 0; j0 < 2048; j0 += 128) {
        __syncthreads();   // prior iteration's smem reads complete (also fences Q writes)
        // ---- stage K, V raw via cp.async ----
#pragma unroll
        for (int i = 0; i < 8; i++) {
            int id = tid + i * 256;              // 0..2047 chunks
            int row = id >> 4;                   // 0..127
            int cf = (id & 15) << 2;             // float col 0..60
            int tok = segbase + off + (j0 + row) * rate;
            const float* src = g_k + ((size_t)tok * NH + head) * HD + cf;
            cp16(ksb + (uint32_t)((row * AKP + cf) * 4), src);
        }
#pragma unroll
        for (int i = 0; i < 8; i++) {
            int id = tid + i * 256;
            int row = id >> 4;
            int cf = (id & 15) << 2;
            int tok = segbase + off + (j0 + row) * rate;
            const float* src = g_v + ((size_t)tok * NH + head) * HD + cf;
            cp16(sb + (uint32_t)((128 * AQP + 128 * AKP + row * AVP + cf) * 4), src);
        }
        CP_COMMIT();
        CP_WAIT0();
        __syncthreads();

#pragma unroll
        for (int ch = 0; ch < 2; ch++) {
            const int jbase = ch * 64;
            // ---- QK: S-frags in registers ----
            float s[8][4];
#pragma unroll
            for (int nt = 0; nt < 8; nt++) { s[nt][0] = s[nt][1] = s[nt][2] = s[nt][3] = 0.f; }
#pragma unroll
            for (int kk = 0; kk < 8; kk++) {
                unsigned qa[4];
                {
                    int r = warp * 16 + a_rl;
                    ldsm4(qa[0], qa[1], qa[2], qa[3],
                          sb + (uint32_t)((r * AQP + kk * 8 + a_cl) * 4));
                }
#pragma unroll
                for (int nt = 0; nt < 8; nt++) {
                    int n = jbase + nt * 8 + b_rl;
                    unsigned kb[2];
                    ldsm2(kb[0], kb[1], ksb + (uint32_t)((n * AKP + kk * 8 + b_cl) * 4));
                    kb[0] = tf32r(kb[0]);
                    kb[1] = tf32r(kb[1]);
                    mma8(s[nt], qa, kb);
                }
            }
            // ---- in-register online softmax (rows lr and lr+8) ----
            float mx0 = -1e30f, mx1 = -1e30f;
#pragma unroll
            for (int nt = 0; nt < 8; nt++) {
                mx0 = fmaxf(mx0, fmaxf(s[nt][0], s[nt][1]));
                mx1 = fmaxf(mx1, fmaxf(s[nt][2], s[nt][3]));
            }
            mx0 = fmaxf(mx0, __shfl_xor_sync(0xffffffffu, mx0, 1));
            mx0 = fmaxf(mx0, __shfl_xor_sync(0xffffffffu, mx0, 2));
            mx1 = fmaxf(mx1, __shfl_xor_sync(0xffffffffu, mx1, 1));
            mx1 = fmaxf(mx1, __shfl_xor_sync(0xffffffffu, mx1, 2));
            float mn0 = fmaxf(m0, mx0), mn1 = fmaxf(m1, mx1);
            float al0 = __expf(m0 - mn0), al1 = __expf(m1 - mn1);
#pragma unroll
            for (int nt = 0; nt < 8; nt++) {
                o[nt][0] *= al0; o[nt][1] *= al0; o[nt][2] *= al1; o[nt][3] *= al1;
            }
            float sum0 = 0.f, sum1 = 0.f;
#pragma unroll
            for (int nt = 0; nt < 8; nt++) {
                float e0 = __expf(s[nt][0] - mn0); sum0 += e0; s[nt][0] = tf32f(e0);
                float e1 = __expf(s[nt][1] - mn0); sum0 += e1; s[nt][1] = tf32f(e1);
                float e2 = __expf(s[nt][2] - mn1); sum1 += e2; s[nt][2] = tf32f(e2);
                float e3 = __expf(s[nt][3] - mn1); sum1 += e3; s[nt][3] = tf32f(e3);
            }
            sum0 += __shfl_xor_sync(0xffffffffu, sum0, 1);
            sum0 += __shfl_xor_sync(0xffffffffu, sum0, 2);
            sum1 += __shfl_xor_sync(0xffffffffu, sum1, 1);
            sum1 += __shfl_xor_sync(0xffffffffu, sum1, 2);
            l0 = l0 * al0 + sum0;
            l1 = l1 * al1 + sum1;
            m0 = mn0; m1 = mn1;

            // ---- PV: shuffle-transpose C-frag -> A-frag, mma with V ----
#pragma unroll
            for (int kk = 0; kk < 8; kk++) {
                unsigned a[4];
                {
                    float u, v;
                    u = __shfl_sync(0xffffffffu, s[kk][0], srcA);
                    v = __shfl_sync(0xffffffffu, s[kk][1], srcA);
                    a[0] = fbits(odd ? v : u);
                    u = __shfl_sync(0xffffffffu, s[kk][2], srcA);
                    v = __shfl_sync(0xffffffffu, s[kk][3], srcA);
                    a[1] = fbits(odd ? v : u);
                    u = __shfl_sync(0xffffffffu, s[kk][0], srcB);
                    v = __shfl_sync(0xffffffffu, s[kk][1], srcB);
                    a[2] = fbits(odd ? v : u);
                    u = __shfl_sync(0xffffffffu, s[kk][2], srcB);
                    v = __shfl_sync(0xffffffffu, s[kk][3], srcB);
                    a[3] = fbits(odd ? v : u);
                }
                const int kr = jbase + kk * 8 + l3;
#pragma unroll
                for (int nto = 0; nto < 8; nto++) {
                    unsigned b[2];
                    b[0] = tf32r(fbits(Vs[kr * AVP + nto * 8 + lr]));
                    b[1] = tf32r(fbits(Vs[(kr + 4) * AVP + nto * 8 + lr]));
                    mma8(o[nto], a, b);
                }
            }
        }
    }

    // ---- epilogue ----
    {
        float inv0 = 1.f / l0;
        float inv1 = 1.f / l1;
        int tok0 = segbase + off + (q0 + warp * 16 + lr) * rate;
        int tok1 = segbase + off + (q0 + warp * 16 + lr + 8) * rate;
#pragma unroll
        for (int nt = 0; nt < 8; nt++) {
            int c = nt * 8 + (l3 << 1);
            *(float2*)(g_x + ((size_t)tok0 * NH + head) * HD + c) =
                make_float2(o[nt][0] * inv0, o[nt][1] * inv0);
            *(float2*)(g_x + ((size_t)tok1 * NH + head) * HD + c) =
                make_float2(o[nt][2] * inv1, o[nt][3] * inv1);
        }
    }
}

// ---------------- LayerNorm ----------------
__global__ __launch_bounds__(256) void ln_kernel(
    const float* __restrict__ x_in, float* __restrict__ y_out,
    const float* __restrict__ gam, const float* __restrict__ bet)
{
    __shared__ float red[16];
    const int row = blockIdx.x;
    const int tid = threadIdx.x;
    const int c = tid * 4;
    const float4 xv = *(const float4*)(x_in + (size_t)row * EMB + c);
    float s = xv.x + xv.y + xv.z + xv.w;
    float s2 = xv.x * xv.x + xv.y * xv.y + xv.z * xv.z + xv.w * xv.w;
#pragma unroll
    for (int o = 16; o; o >>= 1) {
        s += __shfl_xor_sync(0xffffffffu, s, o);
        s2 += __shfl_xor_sync(0xffffffffu, s2, o);
    }
    if ((tid & 31) == 0) { red[tid >> 5] = s; red[8 + (tid >> 5)] = s2; }
    __syncthreads();
    if (tid < 32) {
        float a = (tid < 8) ? red[tid] : 0.f;
        float b = (tid < 8) ? red[8 + tid] : 0.f;
#pragma unroll
        for (int o = 4; o; o >>= 1) {
            a += __shfl_xor_sync(0xffffffffu, a, o);
            b += __shfl_xor_sync(0xffffffffu, b, o);
        }
        if (tid == 0) { red[0] = a; red[1] = b; }
    }
    __syncthreads();
    const float mu = red[0] * (1.f / EMB);
    const float var = red[1] * (1.f / EMB) - mu * mu;
    const float rs = rsqrtf(var + 1e-5f);
    const float4 gv = *(const float4*)(gam + c);
    const float4 bv = *(const float4*)(bet + c);
    float4 ov;
    ov.x = (xv.x - mu) * rs * gv.x + bv.x;
    ov.y = (xv.y - mu) * rs * gv.y + bv.y;
    ov.z = (xv.z - mu) * rs * gv.z + bv.z;
    ov.w = (xv.w - mu) * rs * gv.w + bv.w;
    *(float4*)(y_out + (size_t)row * EMB + c) = ov;
}

// ---------------- launch ----------------
extern "C" void kernel_launch(void* const* d_in, const int* in_sizes, int n_in,
                              void* d_out, int out_size)
{
    (void)in_sizes; (void)n_in; (void)out_size;
    const float* query = (const float*)d_in[0];
    const float* key   = (const float*)d_in[1];
    const float* value = (const float*)d_in[2];
    const float* Wq = (const float*)d_in[3];
    const float* bq = (const float*)d_in[4];
    const float* Wk = (const float*)d_in[5];
    const float* bk = (const float*)d_in[6];
    const float* Wv = (const float*)d_in[7];
    const float* bv = (const float*)d_in[8];
    const float* Wo = (const float*)d_in[9];
    const float* bo = (const float*)d_in[10];
    const float* ln_g = (const float*)d_in[11];
    const float* ln_b = (const float*)d_in[12];
    float* out = (float*)d_out;

    float *pq, *pk, *pv, *px, *pln;
    cudaGetSymbolAddress((void**)&pq, g_q);
    cudaGetSymbolAddress((void**)&pk, g_k);
    cudaGetSymbolAddress((void**)&pv, g_v);
    cudaGetSymbolAddress((void**)&px, g_x);
    cudaGetSymbolAddress((void**)&pln, g_ln);

    zero_kernel<<<(NTOK * EMB / 4) / 256, 256>>>((float4*)px);

    cudaFuncSetAttribute(gemm_mma_kernel, cudaFuncAttributeMaxDynamicSharedMemorySize,
                         GEMM_SMEM_BYTES);
    dim3 ggrid(EMB / 128, NTOK / 128);
    gemm_mma_kernel<<<ggrid, 256, GEMM_SMEM_BYTES>>>(query, Wq, bq, pq, NTOK, EMB, EMB);
    gemm_mma_kernel<<<ggrid, 256, GEMM_SMEM_BYTES>>>(key,   Wk, bk, pk, NTOK, EMB, EMB);
    gemm_mma_kernel<<<ggrid, 256, GEMM_SMEM_BYTES>>>(value, Wv, bv, pv, NTOK, EMB, EMB);

    cudaFuncSetAttribute(attn_kernel, cudaFuncAttributeMaxDynamicSharedMemorySize,
                         ATTN_SMEM_BYTES);
    attn_kernel<<<dim3(16, 39), 256, ATTN_SMEM_BYTES>>>();

    ln_kernel<<<NTOK, 256>>>(px, pln, ln_g, ln_b);

    gemm_mma_kernel<<<ggrid, 256, GEMM_SMEM_BYTES>>>(pln, Wo, bo, out, NTOK, EMB, EMB);
}

// round 10
// speedup vs baseline: 1.8447x; 1.1258x over previous
#include <cuda_runtime.h>
#include <stdint.h>
#include <stddef.h>

#define NTOK 8192
#define EMB  1024
#define NH   16
#define HD   64

// ---------------- scratch (static device globals; no allocation) ----------------
__device__ float g_q[(size_t)NTOK * EMB];
__device__ float g_k[(size_t)NTOK * EMB];
__device__ float g_v[(size_t)NTOK * EMB];
__device__ float g_x[(size_t)NTOK * EMB];
__device__ float g_ln[(size_t)NTOK * EMB];
// pre-rounded inputs / weights
__device__ float g_qi[(size_t)NTOK * EMB];
__device__ float g_ki[(size_t)NTOK * EMB];
__device__ float g_vi[(size_t)NTOK * EMB];
__device__ float g_wq[(size_t)EMB * EMB];
__device__ float g_wk[(size_t)EMB * EMB];
__device__ float g_wv[(size_t)EMB * EMB];
__device__ float g_wo[(size_t)EMB * EMB];

// ---------------- helpers ----------------
__device__ __forceinline__ float tf32f(float x) {
    unsigned u;
    asm("cvt.rna.tf32.f32 %0, %1;" : "=r"(u) : "f"(x));
    return __uint_as_float(u);
}
__device__ __forceinline__ unsigned fbits(float x) { return __float_as_uint(x); }

__device__ __forceinline__ uint32_t smem_u32(const void* p) {
    uint32_t a;
    asm("{ .reg .u64 t; cvta.to.shared.u64 t, %1; cvt.u32.u64 %0, t; }" : "=r"(a) : "l"(p));
    return a;
}

__device__ __forceinline__ void cp16(uint32_t dst, const void* src) {
    asm volatile("cp.async.cg.shared.global [%0], [%1], 16;" :: "r"(dst), "l"(src));
}
#define CP_COMMIT() asm volatile("cp.async.commit_group;" ::: "memory")
#define CP_WAIT1()  asm volatile("cp.async.wait_group 1;" ::: "memory")
#define CP_WAIT0()  asm volatile("cp.async.wait_group 0;" ::: "memory")

__device__ __forceinline__ void ldsm4(unsigned& r0, unsigned& r1, unsigned& r2, unsigned& r3,
                                      uint32_t addr) {
    asm volatile("ldmatrix.sync.aligned.m8n8.x4.shared.b16 {%0,%1,%2,%3}, [%4];"
                 : "=r"(r0), "=r"(r1), "=r"(r2), "=r"(r3) : "r"(addr));
}
__device__ __forceinline__ void ldsm2(unsigned& r0, unsigned& r1, uint32_t addr) {
    asm volatile("ldmatrix.sync.aligned.m8n8.x2.shared.b16 {%0,%1}, [%2];"
                 : "=r"(r0), "=r"(r1) : "r"(addr));
}

__device__ __forceinline__ void mma8(float c[4], const unsigned a[4], const unsigned b[2]) {
    asm volatile(
        "mma.sync.aligned.m16n8k8.row.col.f32.tf32.tf32.f32 "
        "{%0,%1,%2,%3},{%4,%5,%6,%7},{%8,%9},{%0,%1,%2,%3};\n"
        : "+f"(c[0]), "+f"(c[1]), "+f"(c[2]), "+f"(c[3])
        : "r"(a[0]), "r"(a[1]), "r"(a[2]), "r"(a[3]), "r"(b[0]), "r"(b[1]));
}

// ---------------- zero / round ----------------
__global__ void zero_kernel(float4* p) {
    p[(size_t)blockIdx.x * blockDim.x + threadIdx.x] = make_float4(0.f, 0.f, 0.f, 0.f);
}
__global__ void round_kernel(const float4* __restrict__ in, float4* __restrict__ out) {
    size_t i = (size_t)blockIdx.x * blockDim.x + threadIdx.x;
    float4 v = in[i];
    out[i] = make_float4(tf32f(v.x), tf32f(v.y), tf32f(v.z), tf32f(v.w));
}

// ============================================================================
// GEMM: C = A @ W^T + bias.  Operands pre-rounded to tf32 -> NO cvt in loop.
// RND: round epilogue output to tf32 (for Q/K/V feeding attention).
// ============================================================================
#define GKT 32
#define NSTG 3
#define STAGE_FLOATS (2 * 128 * GKT)
#define B_OFF_FLOATS (128 * GKT)
#define GEMM_SMEM_BYTES (NSTG * STAGE_FLOATS * 4)

template <bool RND>
__global__ __launch_bounds__(256, 2) void gemm_mma_kernel(
    const float* __restrict__ A, const float* __restrict__ W,
    const float* __restrict__ bias, float* __restrict__ C,
    int M, int Nn, int K)
{
    extern __shared__ float smf[];
    const uint32_t sb = smem_u32(smf);
    const int tid  = threadIdx.x;
    const int lane = tid & 31;
    const int warp = tid >> 5;
    const int wm_i = warp & 1;
    const int wn_i = warp >> 1;
    const int bm = blockIdx.y * 128;
    const int bn = blockIdx.x * 128;

    const int T = K / GKT;

    auto issue_tile = [&](int t, int buf) {
        const uint32_t base = sb + (uint32_t)buf * (STAGE_FLOATS * 4);
        const float* Ap = A + (size_t)bm * K + t * GKT;
        const float* Wp = W + (size_t)bn * K + t * GKT;
#pragma unroll
        for (int i = 0; i < 4; i++) {
            int id = tid + i * 256;
            int row = id >> 3;
            int c4 = (id & 7) << 2;
            uint32_t off = (uint32_t)(row * 128 + c4 * 4);
            off ^= (uint32_t)((row & 7) << 4);
            cp16(base + off, Ap + (size_t)row * K + c4);
        }
#pragma unroll
        for (int i = 0; i < 4; i++) {
            int id = tid + i * 256;
            int row = id >> 3;
            int c4 = (id & 7) << 2;
            uint32_t off = (uint32_t)(B_OFF_FLOATS * 4 + row * 128 + c4 * 4);
            off ^= (uint32_t)((row & 7) << 4);
            cp16(base + off, Wp + (size_t)row * K + c4);
        }
        CP_COMMIT();
    };

    float acc[4][4][4];
#pragma unroll
    for (int mt = 0; mt < 4; mt++)
#pragma unroll
        for (int nt = 0; nt < 4; nt++)
#pragma unroll
            for (int i = 0; i < 4; i++) acc[mt][nt][i] = 0.f;

    issue_tile(0, 0);
    issue_tile(1, 1);

    const int a_rl = ((lane >> 3) & 1) * 8 + (lane & 7);
    const int a_cl = ((lane >> 4) & 1) * 4;
    const int b_rl = lane & 7;
    const int b_cl = ((lane >> 3) & 1) * 4;

    for (int t = 0; t < T; t++) {
        CP_WAIT1();
        __syncthreads();
        if (t + 2 < T) issue_tile(t + 2, (t + 2) % NSTG);
        else CP_COMMIT();

        const uint32_t base  = sb + (uint32_t)(t % NSTG) * (STAGE_FLOATS * 4);
        const uint32_t bbase = base + B_OFF_FLOATS * 4;

#pragma unroll
        for (int kk = 0; kk < 4; kk++) {
            unsigned af[4][4];
#pragma unroll
            for (int mt = 0; mt < 4; mt++) {
                int r = (wm_i * 4 + mt) * 16 + a_rl;
                int cb = kk * 8 + a_cl;
                uint32_t off = (uint32_t)(r * 128 + cb * 4) ^ (uint32_t)((r & 7) << 4);
                ldsm4(af[mt][0], af[mt][1], af[mt][2], af[mt][3], base + off);
            }
            unsigned bf[4][2];
#pragma unroll
            for (int nt = 0; nt < 4; nt++) {
                int n = (wn_i * 4 + nt) * 8 + b_rl;
                int cb = kk * 8 + b_cl;
                uint32_t off = (uint32_t)(n * 128 + cb * 4) ^ (uint32_t)((n & 7) << 4);
                ldsm2(bf[nt][0], bf[nt][1], bbase + off);
            }
#pragma unroll
            for (int mt = 0; mt < 4; mt++)
#pragma unroll
                for (int nt = 0; nt < 4; nt++)
                    mma8(acc[mt][nt], af[mt], bf[nt]);
        }
    }

    const int l3 = lane & 3;
    const int lr = lane >> 2;
#pragma unroll
    for (int mt = 0; mt < 4; mt++) {
        int r0 = bm + wm_i * 64 + mt * 16 + lr;
#pragma unroll
        for (int nt = 0; nt < 4; nt++) {
            int c = bn + wn_i * 32 + nt * 8 + l3 * 2;
            float b0 = __ldg(bias + c), b1 = __ldg(bias + c + 1);
            float v00 = acc[mt][nt][0] + b0, v01 = acc[mt][nt][1] + b1;
            float v10 = acc[mt][nt][2] + b0, v11 = acc[mt][nt][3] + b1;
            if (RND) { v00 = tf32f(v00); v01 = tf32f(v01); v10 = tf32f(v10); v11 = tf32f(v11); }
            *(float2*)(C + (size_t)r0 * Nn + c)       = make_float2(v00, v01);
            *(float2*)(C + (size_t)(r0 + 8) * Nn + c) = make_float2(v10, v11);
        }
    }
}

// ============================================================================
// Attention: register-resident S, in-warp softmax. K/V/Q pre-rounded -> no cvt.
// ============================================================================
#define AQP 68
#define AKP 68
#define AVP 72
#define ATTN_SMEM_BYTES ((128*AQP + 128*AKP + 128*AVP) * 4)   // 104 KB

__global__ __launch_bounds__(256, 2) void attn_kernel() {
    extern __shared__ float sm[];
    float* Qs = sm;
    float* Vs = sm + 128 * AQP + 128 * AKP;
    const uint32_t sb  = smem_u32(sm);
    const uint32_t ksb = sb + 128 * AQP * 4;

    const int p = blockIdx.y;
    int rate, off, head, segbase;
    if (p < 24)      { rate = 1; off = 0; segbase = (p / 6) * 2048;         head = p % 6; }
    else if (p < 34) { int q = p - 24; rate = 2; off = 1; segbase = (q / 5) * 4096; head = 6 + q % 5; }
    else             { int q = p - 34; rate = 4; off = 2; segbase = 0;             head = 11 + q; }

    const int tid = threadIdx.x;
    const int lane = tid & 31;
    const int warp = tid >> 5;
    const int l3 = lane & 3;
    const int lr = lane >> 2;
    const int q0 = blockIdx.x * 128;
    const float scale = 0.125f;   // power of 2: scaling pre-rounded tf32 is exact

    for (int i = tid; i < 2048; i += 256) {
        int s = i >> 4;
        int c4 = (i & 15) << 2;
        int tok = segbase + off + (q0 + s) * rate;
        const float4 v = *(const float4*)(g_q + ((size_t)tok * NH + head) * HD + c4);
        float* d = Qs + s * AQP + c4;
        d[0] = v.x * scale; d[1] = v.y * scale;
        d[2] = v.z * scale; d[3] = v.w * scale;
    }

    const int a_rl = ((lane >> 3) & 1) * 8 + (lane & 7);
    const int a_cl = ((lane >> 4) & 1) * 4;
    const int b_rl = lane & 7;
    const int b_cl = ((lane >> 3) & 1) * 4;
    const int srcA = (lane & ~3) | (l3 >> 1);
    const int srcB = srcA + 2;
    const bool odd = (l3 & 1);

    float o[8][4];
#pragma unroll
    for (int nt = 0; nt < 8; nt++) { o[nt][0] = o[nt][1] = o[nt][2] = o[nt][3] = 0.f; }
    float m0 = -1e30f, m1 = -1e30f, l0 = 0.f, l1 = 0.f;

    for (int j0 = 0; j0 < 2048; j0 += 128) {
        __syncthreads();
#pragma unroll
        for (int i = 0; i < 8; i++) {
            int id = tid + i * 256;
            int row = id >> 4;
            int cf = (id & 15) << 2;
            int tok = segbase + off + (j0 + row) * rate;
            const float* src = g_k + ((size_t)tok * NH + head) * HD + cf;
            cp16(ksb + (uint32_t)((row * AKP + cf) * 4), src);
        }
#pragma unroll
        for (int i = 0; i < 8; i++) {
            int id = tid + i * 256;
            int row = id >> 4;
            int cf = (id & 15) << 2;
            int tok = segbase + off + (j0 + row) * rate;
            const float* src = g_v + ((size_t)tok * NH + head) * HD + cf;
            cp16(sb + (uint32_t)((128 * AQP + 128 * AKP + row * AVP + cf) * 4), src);
        }
        CP_COMMIT();
        CP_WAIT0();
        __syncthreads();

#pragma unroll
        for (int ch = 0; ch < 2; ch++) {
            const int jbase = ch * 64;
            float s[8][4];
#pragma unroll
            for (int nt = 0; nt < 8; nt++) { s[nt][0] = s[nt][1] = s[nt][2] = s[nt][3] = 0.f; }
#pragma unroll
            for (int kk = 0; kk < 8; kk++) {
                unsigned qa[4];
                {
                    int r = warp * 16 + a_rl;
                    ldsm4(qa[0], qa[1], qa[2], qa[3],
                          sb + (uint32_t)((r * AQP + kk * 8 + a_cl) * 4));
                }
#pragma unroll
                for (int nt = 0; nt < 8; nt++) {
                    int n = jbase + nt * 8 + b_rl;
                    unsigned kb[2];
                    ldsm2(kb[0], kb[1], ksb + (uint32_t)((n * AKP + kk * 8 + b_cl) * 4));
                    mma8(s[nt], qa, kb);
                }
            }
            float mx0 = -1e30f, mx1 = -1e30f;
#pragma unroll
            for (int nt = 0; nt < 8; nt++) {
                mx0 = fmaxf(mx0, fmaxf(s[nt][0], s[nt][1]));
                mx1 = fmaxf(mx1, fmaxf(s[nt][2], s[nt][3]));
            }
            mx0 = fmaxf(mx0, __shfl_xor_sync(0xffffffffu, mx0, 1));
            mx0 = fmaxf(mx0, __shfl_xor_sync(0xffffffffu, mx0, 2));
            mx1 = fmaxf(mx1, __shfl_xor_sync(0xffffffffu, mx1, 1));
            mx1 = fmaxf(mx1, __shfl_xor_sync(0xffffffffu, mx1, 2));
            float mn0 = fmaxf(m0, mx0), mn1 = fmaxf(m1, mx1);
            float al0 = __expf(m0 - mn0), al1 = __expf(m1 - mn1);
#pragma unroll
            for (int nt = 0; nt < 8; nt++) {
                o[nt][0] *= al0; o[nt][1] *= al0; o[nt][2] *= al1; o[nt][3] *= al1;
            }
            float sum0 = 0.f, sum1 = 0.f;
#pragma unroll
            for (int nt = 0; nt < 8; nt++) {
                float e0 = __expf(s[nt][0] - mn0); sum0 += e0; s[nt][0] = tf32f(e0);
                float e1 = __expf(s[nt][1] - mn0); sum0 += e1; s[nt][1] = tf32f(e1);
                float e2 = __expf(s[nt][2] - mn1); sum1 += e2; s[nt][2] = tf32f(e2);
                float e3 = __expf(s[nt][3] - mn1); sum1 += e3; s[nt][3] = tf32f(e3);
            }
            sum0 += __shfl_xor_sync(0xffffffffu, sum0, 1);
            sum0 += __shfl_xor_sync(0xffffffffu, sum0, 2);
            sum1 += __shfl_xor_sync(0xffffffffu, sum1, 1);
            sum1 += __shfl_xor_sync(0xffffffffu, sum1, 2);
            l0 = l0 * al0 + sum0;
            l1 = l1 * al1 + sum1;
            m0 = mn0; m1 = mn1;

#pragma unroll
            for (int kk = 0; kk < 8; kk++) {
                unsigned a[4];
                {
                    float u, v;
                    u = __shfl_sync(0xffffffffu, s[kk][0], srcA);
                    v = __shfl_sync(0xffffffffu, s[kk][1], srcA);
                    a[0] = fbits(odd ? v : u);
                    u = __shfl_sync(0xffffffffu, s[kk][2], srcA);
                    v = __shfl_sync(0xffffffffu, s[kk][3], srcA);
                    a[1] = fbits(odd ? v : u);
                    u = __shfl_sync(0xffffffffu, s[kk][0], srcB);
                    v = __shfl_sync(0xffffffffu, s[kk][1], srcB);
                    a[2] = fbits(odd ? v : u);
                    u = __shfl_sync(0xffffffffu, s[kk][2], srcB);
                    v = __shfl_sync(0xffffffffu, s[kk][3], srcB);
                    a[3] = fbits(odd ? v : u);
                }
                const int kr = jbase + kk * 8 + l3;
#pragma unroll
                for (int nto = 0; nto < 8; nto++) {
                    unsigned b[2];
                    b[0] = fbits(Vs[kr * AVP + nto * 8 + lr]);
                    b[1] = fbits(Vs[(kr + 4) * AVP + nto * 8 + lr]);
                    mma8(o[nto], a, b);
                }
            }
        }
    }

    {
        float inv0 = 1.f / l0;
        float inv1 = 1.f / l1;
        int tok0 = segbase + off + (q0 + warp * 16 + lr) * rate;
        int tok1 = segbase + off + (q0 + warp * 16 + lr + 8) * rate;
#pragma unroll
        for (int nt = 0; nt < 8; nt++) {
            int c = nt * 8 + (l3 << 1);
            *(float2*)(g_x + ((size_t)tok0 * NH + head) * HD + c) =
                make_float2(o[nt][0] * inv0, o[nt][1] * inv0);
            *(float2*)(g_x + ((size_t)tok1 * NH + head) * HD + c) =
                make_float2(o[nt][2] * inv1, o[nt][3] * inv1);
        }
    }
}

// ---------------- LayerNorm (writes tf32-pre-rounded output) ----------------
__global__ __launch_bounds__(256) void ln_kernel(
    const float* __restrict__ x_in, float* __restrict__ y_out,
    const float* __restrict__ gam, const float* __restrict__ bet)
{
    __shared__ float red[16];
    const int row = blockIdx.x;
    const int tid = threadIdx.x;
    const int c = tid * 4;
    const float4 xv = *(const float4*)(x_in + (size_t)row * EMB + c);
    float s = xv.x + xv.y + xv.z + xv.w;
    float s2 = xv.x * xv.x + xv.y * xv.y + xv.z * xv.z + xv.w * xv.w;
#pragma unroll
    for (int o = 16; o; o >>= 1) {
        s += __shfl_xor_sync(0xffffffffu, s, o);
        s2 += __shfl_xor_sync(0xffffffffu, s2, o);
    }
    if ((tid & 31) == 0) { red[tid >> 5] = s; red[8 + (tid >> 5)] = s2; }
    __syncthreads();
    if (tid < 32) {
        float a = (tid < 8) ? red[tid] : 0.f;
        float b = (tid < 8) ? red[8 + tid] : 0.f;
#pragma unroll
        for (int o = 4; o; o >>= 1) {
            a += __shfl_xor_sync(0xffffffffu, a, o);
            b += __shfl_xor_sync(0xffffffffu, b, o);
        }
        if (tid == 0) { red[0] = a; red[1] = b; }
    }
    __syncthreads();
    const float mu = red[0] * (1.f / EMB);
    const float var = red[1] * (1.f / EMB) - mu * mu;
    const float rs = rsqrtf(var + 1e-5f);
    const float4 gv = *(const float4*)(gam + c);
    const float4 bv = *(const float4*)(bet + c);
    float4 ov;
    ov.x = tf32f((xv.x - mu) * rs * gv.x + bv.x);
    ov.y = tf32f((xv.y - mu) * rs * gv.y + bv.y);
    ov.z = tf32f((xv.z - mu) * rs * gv.z + bv.z);
    ov.w = tf32f((xv.w - mu) * rs * gv.w + bv.w);
    *(float4*)(y_out + (size_t)row * EMB + c) = ov;
}

// ---------------- launch ----------------
extern "C" void kernel_launch(void* const* d_in, const int* in_sizes, int n_in,
                              void* d_out, int out_size)
{
    (void)in_sizes; (void)n_in; (void)out_size;
    const float* query = (const float*)d_in[0];
    const float* key   = (const float*)d_in[1];
    const float* value = (const float*)d_in[2];
    const float* Wq = (const float*)d_in[3];
    const float* bq = (const float*)d_in[4];
    const float* Wk = (const float*)d_in[5];
    const float* bk = (const float*)d_in[6];
    const float* Wv = (const float*)d_in[7];
    const float* bv = (const float*)d_in[8];
    const float* Wo = (const float*)d_in[9];
    const float* bo = (const float*)d_in[10];
    const float* ln_g = (const float*)d_in[11];
    const float* ln_b = (const float*)d_in[12];
    float* out = (float*)d_out;

    float *pq, *pk, *pv, *px, *pln, *pqi, *pki, *pvi, *pwq, *pwk, *pwv, *pwo;
    cudaGetSymbolAddress((void**)&pq, g_q);
    cudaGetSymbolAddress((void**)&pk, g_k);
    cudaGetSymbolAddress((void**)&pv, g_v);
    cudaGetSymbolAddress((void**)&px, g_x);
    cudaGetSymbolAddress((void**)&pln, g_ln);
    cudaGetSymbolAddress((void**)&pqi, g_qi);
    cudaGetSymbolAddress((void**)&pki, g_ki);
    cudaGetSymbolAddress((void**)&pvi, g_vi);
    cudaGetSymbolAddress((void**)&pwq, g_wq);
    cudaGetSymbolAddress((void**)&pwk, g_wk);
    cudaGetSymbolAddress((void**)&pwv, g_wv);
    cudaGetSymbolAddress((void**)&pwo, g_wo);

    const int NB_IN = (NTOK * EMB / 4) / 256;   // 8192 blocks
    const int NB_W  = (EMB * EMB / 4) / 256;    // 1024 blocks

    zero_kernel<<<NB_IN, 256>>>((float4*)px);
    round_kernel<<<NB_IN, 256>>>((const float4*)query, (float4*)pqi);
    round_kernel<<<NB_IN, 256>>>((const float4*)key,   (float4*)pki);
    round_kernel<<<NB_IN, 256>>>((const float4*)value, (float4*)pvi);
    round_kernel<<<NB_W, 256>>>((const float4*)Wq, (float4*)pwq);
    round_kernel<<<NB_W, 256>>>((const float4*)Wk, (float4*)pwk);
    round_kernel<<<NB_W, 256>>>((const float4*)Wv, (float4*)pwv);
    round_kernel<<<NB_W, 256>>>((const float4*)Wo, (float4*)pwo);

    cudaFuncSetAttribute(gemm_mma_kernel<true>,
                         cudaFuncAttributeMaxDynamicSharedMemorySize, GEMM_SMEM_BYTES);
    cudaFuncSetAttribute(gemm_mma_kernel<false>,
                         cudaFuncAttributeMaxDynamicSharedMemorySize, GEMM_SMEM_BYTES);
    dim3 ggrid(EMB / 128, NTOK / 128);
    gemm_mma_kernel<true><<<ggrid, 256, GEMM_SMEM_BYTES>>>(pqi, pwq, bq, pq, NTOK, EMB, EMB);
    gemm_mma_kernel<true><<<ggrid, 256, GEMM_SMEM_BYTES>>>(pki, pwk, bk, pk, NTOK, EMB, EMB);
    gemm_mma_kernel<true><<<ggrid, 256, GEMM_SMEM_BYTES>>>(pvi, pwv, bv, pv, NTOK, EMB, EMB);

    cudaFuncSetAttribute(attn_kernel, cudaFuncAttributeMaxDynamicSharedMemorySize,
                         ATTN_SMEM_BYTES);
    attn_kernel<<<dim3(16, 39), 256, ATTN_SMEM_BYTES>>>();

    ln_kernel<<<NTOK, 256>>>(px, pln, ln_g, ln_b);

    gemm_mma_kernel<false><<<ggrid, 256, GEMM_SMEM_BYTES>>>(pln, pwo, bo, out, NTOK, EMB, EMB);
}

// round 11
// speedup vs baseline: 1.8923x; 1.0258x over previous
#include <cuda_runtime.h>
#include <stdint.h>
#include <stddef.h>

#define NTOK 8192
#define EMB  1024
#define NH   16
#define HD   64

// ---------------- scratch (static device globals; no allocation) ----------------
__device__ float g_q[(size_t)NTOK * EMB];
__device__ float g_k[(size_t)NTOK * EMB];
__device__ float g_v[(size_t)NTOK * EMB];
__device__ float g_x[(size_t)NTOK * EMB];
__device__ float g_ln[(size_t)NTOK * EMB];
// pre-rounded inputs / weights
__device__ float g_qi[(size_t)NTOK * EMB];
__device__ float g_ki[(size_t)NTOK * EMB];
__device__ float g_vi[(size_t)NTOK * EMB];
__device__ float g_wq[(size_t)EMB * EMB];
__device__ float g_wk[(size_t)EMB * EMB];
__device__ float g_wv[(size_t)EMB * EMB];
__device__ float g_wo[(size_t)EMB * EMB];

// ---------------- helpers ----------------
__device__ __forceinline__ float tf32f(float x) {
    unsigned u;
    asm("cvt.rna.tf32.f32 %0, %1;" : "=r"(u) : "f"(x));
    return __uint_as_float(u);
}
__device__ __forceinline__ unsigned fbits(float x) { return __float_as_uint(x); }

__device__ __forceinline__ uint32_t smem_u32(const void* p) {
    uint32_t a;
    asm("{ .reg .u64 t; cvta.to.shared.u64 t, %1; cvt.u32.u64 %0, t; }" : "=r"(a) : "l"(p));
    return a;
}

__device__ __forceinline__ void cp16(uint32_t dst, const void* src) {
    asm volatile("cp.async.cg.shared.global [%0], [%1], 16;" :: "r"(dst), "l"(src));
}
#define CP_COMMIT() asm volatile("cp.async.commit_group;" ::: "memory")
#define CP_WAIT1()  asm volatile("cp.async.wait_group 1;" ::: "memory")
#define CP_WAIT0()  asm volatile("cp.async.wait_group 0;" ::: "memory")

__device__ __forceinline__ void ldsm4(unsigned& r0, unsigned& r1, unsigned& r2, unsigned& r3,
                                      uint32_t addr) {
    asm volatile("ldmatrix.sync.aligned.m8n8.x4.shared.b16 {%0,%1,%2,%3}, [%4];"
                 : "=r"(r0), "=r"(r1), "=r"(r2), "=r"(r3) : "r"(addr));
}
__device__ __forceinline__ void ldsm2(unsigned& r0, unsigned& r1, uint32_t addr) {
    asm volatile("ldmatrix.sync.aligned.m8n8.x2.shared.b16 {%0,%1}, [%2];"
                 : "=r"(r0), "=r"(r1) : "r"(addr));
}

__device__ __forceinline__ void mma8(float c[4], const unsigned a[4], const unsigned b[2]) {
    asm volatile(
        "mma.sync.aligned.m16n8k8.row.col.f32.tf32.tf32.f32 "
        "{%0,%1,%2,%3},{%4,%5,%6,%7},{%8,%9},{%0,%1,%2,%3};\n"
        : "+f"(c[0]), "+f"(c[1]), "+f"(c[2]), "+f"(c[3])
        : "r"(a[0]), "r"(a[1]), "r"(a[2]), "r"(a[3]), "r"(b[0]), "r"(b[1]));
}

// ---------------- zero / round ----------------
__global__ void zero_kernel(float4* p) {
    p[(size_t)blockIdx.x * blockDim.x + threadIdx.x] = make_float4(0.f, 0.f, 0.f, 0.f);
}
__global__ void round_kernel(const float4* __restrict__ in, float4* __restrict__ out) {
    size_t i = (size_t)blockIdx.x * blockDim.x + threadIdx.x;
    float4 v = in[i];
    out[i] = make_float4(tf32f(v.x), tf32f(v.y), tf32f(v.z), tf32f(v.w));
}

// ============================================================================
// GEMM (R10, unchanged): operands pre-rounded, no cvt in loop.
// ============================================================================
#define GKT 32
#define NSTG 3
#define STAGE_FLOATS (2 * 128 * GKT)
#define B_OFF_FLOATS (128 * GKT)
#define GEMM_SMEM_BYTES (NSTG * STAGE_FLOATS * 4)

template <bool RND>
__global__ __launch_bounds__(256, 2) void gemm_mma_kernel(
    const float* __restrict__ A, const float* __restrict__ W,
    const float* __restrict__ bias, float* __restrict__ C,
    int M, int Nn, int K)
{
    extern __shared__ float smf[];
    const uint32_t sb = smem_u32(smf);
    const int tid  = threadIdx.x;
    const int lane = tid & 31;
    const int warp = tid >> 5;
    const int wm_i = warp & 1;
    const int wn_i = warp >> 1;
    const int bm = blockIdx.y * 128;
    const int bn = blockIdx.x * 128;

    const int T = K / GKT;

    auto issue_tile = [&](int t, int buf) {
        const uint32_t base = sb + (uint32_t)buf * (STAGE_FLOATS * 4);
        const float* Ap = A + (size_t)bm * K + t * GKT;
        const float* Wp = W + (size_t)bn * K + t * GKT;
#pragma unroll
        for (int i = 0; i < 4; i++) {
            int id = tid + i * 256;
            int row = id >> 3;
            int c4 = (id & 7) << 2;
            uint32_t off = (uint32_t)(row * 128 + c4 * 4);
            off ^= (uint32_t)((row & 7) << 4);
            cp16(base + off, Ap + (size_t)row * K + c4);
        }
#pragma unroll
        for (int i = 0; i < 4; i++) {
            int id = tid + i * 256;
            int row = id >> 3;
            int c4 = (id & 7) << 2;
            uint32_t off = (uint32_t)(B_OFF_FLOATS * 4 + row * 128 + c4 * 4);
            off ^= (uint32_t)((row & 7) << 4);
            cp16(base + off, Wp + (size_t)row * K + c4);
        }
        CP_COMMIT();
    };

    float acc[4][4][4];
#pragma unroll
    for (int mt = 0; mt < 4; mt++)
#pragma unroll
        for (int nt = 0; nt < 4; nt++)
#pragma unroll
            for (int i = 0; i < 4; i++) acc[mt][nt][i] = 0.f;

    issue_tile(0, 0);
    issue_tile(1, 1);

    const int a_rl = ((lane >> 3) & 1) * 8 + (lane & 7);
    const int a_cl = ((lane >> 4) & 1) * 4;
    const int b_rl = lane & 7;
    const int b_cl = ((lane >> 3) & 1) * 4;

    for (int t = 0; t < T; t++) {
        CP_WAIT1();
        __syncthreads();
        if (t + 2 < T) issue_tile(t + 2, (t + 2) % NSTG);
        else CP_COMMIT();

        const uint32_t base  = sb + (uint32_t)(t % NSTG) * (STAGE_FLOATS * 4);
        const uint32_t bbase = base + B_OFF_FLOATS * 4;

#pragma unroll
        for (int kk = 0; kk < 4; kk++) {
            unsigned af[4][4];
#pragma unroll
            for (int mt = 0; mt < 4; mt++) {
                int r = (wm_i * 4 + mt) * 16 + a_rl;
                int cb = kk * 8 + a_cl;
                uint32_t off = (uint32_t)(r * 128 + cb * 4) ^ (uint32_t)((r & 7) << 4);
                ldsm4(af[mt][0], af[mt][1], af[mt][2], af[mt][3], base + off);
            }
            unsigned bf[4][2];
#pragma unroll
            for (int nt = 0; nt < 4; nt++) {
                int n = (wn_i * 4 + nt) * 8 + b_rl;
                int cb = kk * 8 + b_cl;
                uint32_t off = (uint32_t)(n * 128 + cb * 4) ^ (uint32_t)((n & 7) << 4);
                ldsm2(bf[nt][0], bf[nt][1], bbase + off);
            }
#pragma unroll
            for (int mt = 0; mt < 4; mt++)
#pragma unroll
                for (int nt = 0; nt < 4; nt++)
                    mma8(acc[mt][nt], af[mt], bf[nt]);
        }
    }

    const int l3 = lane & 3;
    const int lr = lane >> 2;
#pragma unroll
    for (int mt = 0; mt < 4; mt++) {
        int r0 = bm + wm_i * 64 + mt * 16 + lr;
#pragma unroll
        for (int nt = 0; nt < 4; nt++) {
            int c = bn + wn_i * 32 + nt * 8 + l3 * 2;
            float b0 = __ldg(bias + c), b1 = __ldg(bias + c + 1);
            float v00 = acc[mt][nt][0] + b0, v01 = acc[mt][nt][1] + b1;
            float v10 = acc[mt][nt][2] + b0, v11 = acc[mt][nt][3] + b1;
            if (RND) { v00 = tf32f(v00); v01 = tf32f(v01); v10 = tf32f(v10); v11 = tf32f(v11); }
            *(float2*)(C + (size_t)r0 * Nn + c)       = make_float2(v00, v01);
            *(float2*)(C + (size_t)(r0 + 8) * Nn + c) = make_float2(v10, v11);
        }
    }
}

// ============================================================================
// Attention: j-block 64 with DOUBLE-BUFFERED cp.async K/V (load hides under
// compute). Register-resident S, in-warp softmax. Same numerics as R10
// (softmax already updated per 64-col chunk).
// ============================================================================
#define AQP 68
#define AKP 68
#define AVP 72
#define KBUF_B (64 * AKP * 4)     // 17408
#define VBUF_B (64 * AVP * 4)     // 18432
#define Q_B    (128 * AQP * 4)    // 34816
#define ATTN_SMEM_BYTES (Q_B + 2 * KBUF_B + 2 * VBUF_B)   // 106496 = 104 KB

__global__ __launch_bounds__(256, 2) void attn_kernel() {
    extern __shared__ float sm[];
    const uint32_t sb = smem_u32(sm);
    const uint32_t kb0 = sb + Q_B;
    const uint32_t vb0 = sb + Q_B + 2 * KBUF_B;

    const int p = blockIdx.y;
    int rate, off, head, segbase;
    if (p < 24)      { rate = 1; off = 0; segbase = (p / 6) * 2048;         head = p % 6; }
    else if (p < 34) { int q = p - 24; rate = 2; off = 1; segbase = (q / 5) * 4096; head = 6 + q % 5; }
    else             { int q = p - 34; rate = 4; off = 2; segbase = 0;             head = 11 + q; }

    const int tid = threadIdx.x;
    const int lane = tid & 31;
    const int warp = tid >> 5;
    const int l3 = lane & 3;
    const int lr = lane >> 2;
    const int q0 = blockIdx.x * 128;
    const float scale = 0.125f;   // power of 2: scaling pre-rounded tf32 is exact

    // ---- Q staging: scaled, pitch AQP (already tf32-rounded by producer) ----
    for (int i = tid; i < 2048; i += 256) {
        int s = i >> 4;
        int c4 = (i & 15) << 2;
        int tok = segbase + off + (q0 + s) * rate;
        const float4 v = *(const float4*)(g_q + ((size_t)tok * NH + head) * HD + c4);
        float* d = sm + s * AQP + c4;
        d[0] = v.x * scale; d[1] = v.y * scale;
        d[2] = v.z * scale; d[3] = v.w * scale;
    }

    // ---- K/V block issuer: 64 rows, 4 cp16 per thread each ----
    auto issue_kv = [&](int t, int buf) {
        const uint32_t kd = kb0 + (uint32_t)buf * KBUF_B;
        const uint32_t vd = vb0 + (uint32_t)buf * VBUF_B;
#pragma unroll
        for (int i = 0; i < 4; i++) {
            int id = tid + i * 256;              // 0..1023
            int row = id >> 4;                   // 0..63
            int cf = (id & 15) << 2;
            int tok = segbase + off + (t * 64 + row) * rate;
            cp16(kd + (uint32_t)((row * AKP + cf) * 4),
                 g_k + ((size_t)tok * NH + head) * HD + cf);
        }
#pragma unroll
        for (int i = 0; i < 4; i++) {
            int id = tid + i * 256;
            int row = id >> 4;
            int cf = (id & 15) << 2;
            int tok = segbase + off + (t * 64 + row) * rate;
            cp16(vd + (uint32_t)((row * AVP + cf) * 4),
                 g_v + ((size_t)tok * NH + head) * HD + cf);
        }
        CP_COMMIT();
    };

    const int a_rl = ((lane >> 3) & 1) * 8 + (lane & 7);
    const int a_cl = ((lane >> 4) & 1) * 4;
    const int b_rl = lane & 7;
    const int b_cl = ((lane >> 3) & 1) * 4;
    const int srcA = (lane & ~3) | (l3 >> 1);
    const int srcB = srcA + 2;
    const bool odd = (l3 & 1);

    float o[8][4];
#pragma unroll
    for (int nt = 0; nt < 8; nt++) { o[nt][0] = o[nt][1] = o[nt][2] = o[nt][3] = 0.f; }
    float m0 = -1e30f, m1 = -1e30f, l0 = 0.f, l1 = 0.f;

    issue_kv(0, 0);

    const int T = 2048 / 64;   // 32 blocks
    for (int t = 0; t < T; t++) {
        if (t + 1 < T) { issue_kv(t + 1, (t + 1) & 1); CP_WAIT1(); }
        else           { CP_WAIT0(); }
        __syncthreads();   // block t visible to all; Q writes fenced on t==0

        const uint32_t kd = kb0 + (uint32_t)(t & 1) * KBUF_B;
        const float* Vsb = sm + (Q_B + 2 * KBUF_B + (t & 1) * VBUF_B) / 4;

        // ---- QK: S-frags in registers (64 cols) ----
        float s[8][4];
#pragma unroll
        for (int nt = 0; nt < 8; nt++) { s[nt][0] = s[nt][1] = s[nt][2] = s[nt][3] = 0.f; }
#pragma unroll
        for (int kk = 0; kk < 8; kk++) {
            unsigned qa[4];
            {
                int r = warp * 16 + a_rl;
                ldsm4(qa[0], qa[1], qa[2], qa[3],
                      sb + (uint32_t)((r * AQP + kk * 8 + a_cl) * 4));
            }
#pragma unroll
            for (int nt = 0; nt < 8; nt++) {
                int n = nt * 8 + b_rl;
                unsigned kbr[2];
                ldsm2(kbr[0], kbr[1], kd + (uint32_t)((n * AKP + kk * 8 + b_cl) * 4));
                mma8(s[nt], qa, kbr);
            }
        }
        // ---- in-register online softmax (rows lr and lr+8) ----
        float mx0 = -1e30f, mx1 = -1e30f;
#pragma unroll
        for (int nt = 0; nt < 8; nt++) {
            mx0 = fmaxf(mx0, fmaxf(s[nt][0], s[nt][1]));
            mx1 = fmaxf(mx1, fmaxf(s[nt][2], s[nt][3]));
        }
        mx0 = fmaxf(mx0, __shfl_xor_sync(0xffffffffu, mx0, 1));
        mx0 = fmaxf(mx0, __shfl_xor_sync(0xffffffffu, mx0, 2));
        mx1 = fmaxf(mx1, __shfl_xor_sync(0xffffffffu, mx1, 1));
        mx1 = fmaxf(mx1, __shfl_xor_sync(0xffffffffu, mx1, 2));
        float mn0 = fmaxf(m0, mx0), mn1 = fmaxf(m1, mx1);
        float al0 = __expf(m0 - mn0), al1 = __expf(m1 - mn1);
#pragma unroll
        for (int nt = 0; nt < 8; nt++) {
            o[nt][0] *= al0; o[nt][1] *= al0; o[nt][2] *= al1; o[nt][3] *= al1;
        }
        float sum0 = 0.f, sum1 = 0.f;
#pragma unroll
        for (int nt = 0; nt < 8; nt++) {
            float e0 = __expf(s[nt][0] - mn0); sum0 += e0; s[nt][0] = tf32f(e0);
            float e1 = __expf(s[nt][1] - mn0); sum0 += e1; s[nt][1] = tf32f(e1);
            float e2 = __expf(s[nt][2] - mn1); sum1 += e2; s[nt][2] = tf32f(e2);
            float e3 = __expf(s[nt][3] - mn1); sum1 += e3; s[nt][3] = tf32f(e3);
        }
        sum0 += __shfl_xor_sync(0xffffffffu, sum0, 1);
        sum0 += __shfl_xor_sync(0xffffffffu, sum0, 2);
        sum1 += __shfl_xor_sync(0xffffffffu, sum1, 1);
        sum1 += __shfl_xor_sync(0xffffffffu, sum1, 2);
        l0 = l0 * al0 + sum0;
        l1 = l1 * al1 + sum1;
        m0 = mn0; m1 = mn1;

        // ---- PV: shuffle-transpose C-frag -> A-frag, mma with V ----
#pragma unroll
        for (int kk = 0; kk < 8; kk++) {
            unsigned a[4];
            {
                float u, v;
                u = __shfl_sync(0xffffffffu, s[kk][0], srcA);
                v = __shfl_sync(0xffffffffu, s[kk][1], srcA);
                a[0] = fbits(odd ? v : u);
                u = __shfl_sync(0xffffffffu, s[kk][2], srcA);
                v = __shfl_sync(0xffffffffu, s[kk][3], srcA);
                a[1] = fbits(odd ? v : u);
                u = __shfl_sync(0xffffffffu, s[kk][0], srcB);
                v = __shfl_sync(0xffffffffu, s[kk][1], srcB);
                a[2] = fbits(odd ? v : u);
                u = __shfl_sync(0xffffffffu, s[kk][2], srcB);
                v = __shfl_sync(0xffffffffu, s[kk][3], srcB);
                a[3] = fbits(odd ? v : u);
            }
            const int kr = kk * 8 + l3;
#pragma unroll
            for (int nto = 0; nto < 8; nto++) {
                unsigned b[2];
                b[0] = fbits(Vsb[kr * AVP + nto * 8 + lr]);
                b[1] = fbits(Vsb[(kr + 4) * AVP + nto * 8 + lr]);
                mma8(o[nto], a, b);
            }
        }
        __syncthreads();   // all warps done with buf (t&1) before t+2 overwrites it
    }

    // ---- epilogue ----
    {
        float inv0 = 1.f / l0;
        float inv1 = 1.f / l1;
        int tok0 = segbase + off + (q0 + warp * 16 + lr) * rate;
        int tok1 = segbase + off + (q0 + warp * 16 + lr + 8) * rate;
#pragma unroll
        for (int nt = 0; nt < 8; nt++) {
            int c = nt * 8 + (l3 << 1);
            *(float2*)(g_x + ((size_t)tok0 * NH + head) * HD + c) =
                make_float2(o[nt][0] * inv0, o[nt][1] * inv0);
            *(float2*)(g_x + ((size_t)tok1 * NH + head) * HD + c) =
                make_float2(o[nt][2] * inv1, o[nt][3] * inv1);
        }
    }
}

// ---------------- LayerNorm (writes tf32-pre-rounded output) ----------------
__global__ __launch_bounds__(256) void ln_kernel(
    const float* __restrict__ x_in, float* __restrict__ y_out,
    const float* __restrict__ gam, const float* __restrict__ bet)
{
    __shared__ float red[16];
    const int row = blockIdx.x;
    const int tid = threadIdx.x;
    const int c = tid * 4;
    const float4 xv = *(const float4*)(x_in + (size_t)row * EMB + c);
    float s = xv.x + xv.y + xv.z + xv.w;
    float s2 = xv.x * xv.x + xv.y * xv.y + xv.z * xv.z + xv.w * xv.w;
#pragma unroll
    for (int o = 16; o; o >>= 1) {
        s += __shfl_xor_sync(0xffffffffu, s, o);
        s2 += __shfl_xor_sync(0xffffffffu, s2, o);
    }
    if ((tid & 31) == 0) { red[tid >> 5] = s; red[8 + (tid >> 5)] = s2; }
    __syncthreads();
    if (tid < 32) {
        float a = (tid < 8) ? red[tid] : 0.f;
        float b = (tid < 8) ? red[8 + tid] : 0.f;
#pragma unroll
        for (int o = 4; o; o >>= 1) {
            a += __shfl_xor_sync(0xffffffffu, a, o);
            b += __shfl_xor_sync(0xffffffffu, b, o);
        }
        if (tid == 0) { red[0] = a; red[1] = b; }
    }
    __syncthreads();
    const float mu = red[0] * (1.f / EMB);
    const float var = red[1] * (1.f / EMB) - mu * mu;
    const float rs = rsqrtf(var + 1e-5f);
    const float4 gv = *(const float4*)(gam + c);
    const float4 bv = *(const float4*)(bet + c);
    float4 ov;
    ov.x = tf32f((xv.x - mu) * rs * gv.x + bv.x);
    ov.y = tf32f((xv.y - mu) * rs * gv.y + bv.y);
    ov.z = tf32f((xv.z - mu) * rs * gv.z + bv.z);
    ov.w = tf32f((xv.w - mu) * rs * gv.w + bv.w);
    *(float4*)(y_out + (size_t)row * EMB + c) = ov;
}

// ---------------- launch ----------------
extern "C" void kernel_launch(void* const* d_in, const int* in_sizes, int n_in,
                              void* d_out, int out_size)
{
    (void)in_sizes; (void)n_in; (void)out_size;
    const float* query = (const float*)d_in[0];
    const float* key   = (const float*)d_in[1];
    const float* value = (const float*)d_in[2];
    const float* Wq = (const float*)d_in[3];
    const float* bq = (const float*)d_in[4];
    const float* Wk = (const float*)d_in[5];
    const float* bk = (const float*)d_in[6];
    const float* Wv = (const float*)d_in[7];
    const float* bv = (const float*)d_in[8];
    const float* Wo = (const float*)d_in[9];
    const float* bo = (const float*)d_in[10];
    const float* ln_g = (const float*)d_in[11];
    const float* ln_b = (const float*)d_in[12];
    float* out = (float*)d_out;

    float *pq, *pk, *pv, *px, *pln, *pqi, *pki, *pvi, *pwq, *pwk, *pwv, *pwo;
    cudaGetSymbolAddress((void**)&pq, g_q);
    cudaGetSymbolAddress((void**)&pk, g_k);
    cudaGetSymbolAddress((void**)&pv, g_v);
    cudaGetSymbolAddress((void**)&px, g_x);
    cudaGetSymbolAddress((void**)&pln, g_ln);
    cudaGetSymbolAddress((void**)&pqi, g_qi);
    cudaGetSymbolAddress((void**)&pki, g_ki);
    cudaGetSymbolAddress((void**)&pvi, g_vi);
    cudaGetSymbolAddress((void**)&pwq, g_wq);
    cudaGetSymbolAddress((void**)&pwk, g_wk);
    cudaGetSymbolAddress((void**)&pwv, g_wv);
    cudaGetSymbolAddress((void**)&pwo, g_wo);

    const int NB_IN = (NTOK * EMB / 4) / 256;
    const int NB_W  = (EMB * EMB / 4) / 256;

    zero_kernel<<<NB_IN, 256>>>((float4*)px);
    round_kernel<<<NB_IN, 256>>>((const float4*)query, (float4*)pqi);
    round_kernel<<<NB_IN, 256>>>((const float4*)key,   (float4*)pki);
    round_kernel<<<NB_IN, 256>>>((const float4*)value, (float4*)pvi);
    round_kernel<<<NB_W, 256>>>((const float4*)Wq, (float4*)pwq);
    round_kernel<<<NB_W, 256>>>((const float4*)Wk, (float4*)pwk);
    round_kernel<<<NB_W, 256>>>((const float4*)Wv, (float4*)pwv);
    round_kernel<<<NB_W, 256>>>((const float4*)Wo, (float4*)pwo);

    cudaFuncSetAttribute(gemm_mma_kernel<true>,
                         cudaFuncAttributeMaxDynamicSharedMemorySize, GEMM_SMEM_BYTES);
    cudaFuncSetAttribute(gemm_mma_kernel<false>,
                         cudaFuncAttributeMaxDynamicSharedMemorySize, GEMM_SMEM_BYTES);
    dim3 ggrid(EMB / 128, NTOK / 128);
    gemm_mma_kernel<true><<<ggrid, 256, GEMM_SMEM_BYTES>>>(pqi, pwq, bq, pq, NTOK, EMB, EMB);
    gemm_mma_kernel<true><<<ggrid, 256, GEMM_SMEM_BYTES>>>(pki, pwk, bk, pk, NTOK, EMB, EMB);
    gemm_mma_kernel<true><<<ggrid, 256, GEMM_SMEM_BYTES>>>(pvi, pwv, bv, pv, NTOK, EMB, EMB);

    cudaFuncSetAttribute(attn_kernel, cudaFuncAttributeMaxDynamicSharedMemorySize,
                         ATTN_SMEM_BYTES);
    attn_kernel<<<dim3(16, 39), 256, ATTN_SMEM_BYTES>>>();

    ln_kernel<<<NTOK, 256>>>(px, pln, ln_g, ln_b);

    gemm_mma_kernel<false><<<ggrid, 256, GEMM_SMEM_BYTES>>>(pln, pwo, bo, out, NTOK, EMB, EMB);
}

// round 14
// speedup vs baseline: 2.0931x; 1.1061x over previous
#include <cuda_runtime.h>
#include <stdint.h>
#include <stddef.h>

#define NTOK 8192
#define EMB  1024
#define NH   16
#define HD   64

// ---------------- scratch (static device globals; no allocation) ----------------
__device__ float g_q[(size_t)NTOK * EMB];
__device__ float g_k[(size_t)NTOK * EMB];
__device__ float g_v[(size_t)NTOK * EMB];
__device__ float g_x[(size_t)NTOK * EMB];
__device__ float g_ln[(size_t)NTOK * EMB];
__device__ float g_qi[(size_t)NTOK * EMB];
__device__ float g_ki[(size_t)NTOK * EMB];
__device__ float g_vi[(size_t)NTOK * EMB];
__device__ float g_wq[(size_t)EMB * EMB];
__device__ float g_wk[(size_t)EMB * EMB];
__device__ float g_wv[(size_t)EMB * EMB];
__device__ float g_wo[(size_t)EMB * EMB];

// ---------------- helpers ----------------
__device__ __forceinline__ float tf32f(float x) {
    unsigned u;
    asm("cvt.rna.tf32.f32 %0, %1;" : "=r"(u) : "f"(x));
    return __uint_as_float(u);
}
__device__ __forceinline__ unsigned fbits(float x) { return __float_as_uint(x); }

__device__ __forceinline__ uint32_t smem_u32(const void* p) {
    uint32_t a;
    asm("{ .reg .u64 t; cvta.to.shared.u64 t, %1; cvt.u32.u64 %0, t; }" : "=r"(a) : "l"(p));
    return a;
}

__device__ __forceinline__ void cp16(uint32_t dst, const void* src) {
    asm volatile("cp.async.cg.shared.global [%0], [%1], 16;" :: "r"(dst), "l"(src));
}
#define CP_COMMIT() asm volatile("cp.async.commit_group;" ::: "memory")
#define CP_WAIT1()  asm volatile("cp.async.wait_group 1;" ::: "memory")
#define CP_WAIT0()  asm volatile("cp.async.wait_group 0;" ::: "memory")

__device__ __forceinline__ void ldsm4(unsigned& r0, unsigned& r1, unsigned& r2, unsigned& r3,
                                      uint32_t addr) {
    asm volatile("ldmatrix.sync.aligned.m8n8.x4.shared.b16 {%0,%1,%2,%3}, [%4];"
                 : "=r"(r0), "=r"(r1), "=r"(r2), "=r"(r3) : "r"(addr));
}
__device__ __forceinline__ void ldsm2(unsigned& r0, unsigned& r1, uint32_t addr) {
    asm volatile("ldmatrix.sync.aligned.m8n8.x2.shared.b16 {%0,%1}, [%2];"
                 : "=r"(r0), "=r"(r1) : "r"(addr));
}

__device__ __forceinline__ void mma8(float c[4], const unsigned a[4], const unsigned b[2]) {
    asm volatile(
        "mma.sync.aligned.m16n8k8.row.col.f32.tf32.tf32.f32 "
        "{%0,%1,%2,%3},{%4,%5,%6,%7},{%8,%9},{%0,%1,%2,%3};\n"
        : "+f"(c[0]), "+f"(c[1]), "+f"(c[2]), "+f"(c[3])
        : "r"(a[0]), "r"(a[1]), "r"(a[2]), "r"(a[3]), "r"(b[0]), "r"(b[1]));
}

// ---------------- fused preamble: zero g_x + round inputs/weights ----------------
#define SEG4  (NTOK * EMB / 4)      // 2097152 float4 per activation
#define WSEG4 (EMB * EMB / 4)       // 262144 float4 per weight
#define PREP_TOTAL4 (4 * SEG4 + 4 * WSEG4)
#define PREP_BLOCKS (PREP_TOTAL4 / 256)

__global__ void prep_kernel(const float4* __restrict__ q, const float4* __restrict__ k,
                            const float4* __restrict__ v,
                            const float4* __restrict__ wq, const float4* __restrict__ wk,
                            const float4* __restrict__ wv, const float4* __restrict__ wo,
                            float4* __restrict__ x0,
                            float4* __restrict__ qi, float4* __restrict__ ki,
                            float4* __restrict__ vi,
                            float4* __restrict__ owq, float4* __restrict__ owk,
                            float4* __restrict__ owv, float4* __restrict__ owo)
{
    size_t i = (size_t)blockIdx.x * 256 + threadIdx.x;
    if (i < SEG4) { x0[i] = make_float4(0.f, 0.f, 0.f, 0.f); return; }
    i -= SEG4;
    const float4* src;
    float4* dst;
    if (i < 3 * (size_t)SEG4) {
        size_t s = i / SEG4;
        i -= s * SEG4;
        src = (s == 0) ? q : (s == 1) ? k : v;
        dst = (s == 0) ? qi : (s == 1) ? ki : vi;
    } else {
        i -= 3 * (size_t)SEG4;
        size_t s = i / WSEG4;
        i -= s * WSEG4;
        src = (s == 0) ? wq : (s == 1) ? wk : (s == 2) ? wv : wo;
        dst = (s == 0) ? owq : (s == 1) ? owk : (s == 2) ? owv : owo;
    }
    float4 val = src[i];
    dst[i] = make_float4(tf32f(val.x), tf32f(val.y), tf32f(val.z), tf32f(val.w));
}

// ============================================================================
// GEMM core (compile-time dims M=NTOK, N=K=EMB): operands pre-rounded tf32.
// CTA tile 128x128, 8 warps 2x4, warp 64x32, KT=32, 3-stage cp.async, 2 CTA/SM.
// ============================================================================
#define GKT 32
#define NSTG 3
#define STAGE_FLOATS (2 * 128 * GKT)
#define B_OFF_FLOATS (128 * GKT)
#define GEMM_SMEM_BYTES (NSTG * STAGE_FLOATS * 4)

template <bool RND>
__device__ __forceinline__ void gemm_core(
    const float* __restrict__ A, const float* __restrict__ W,
    const float* __restrict__ bias, float* __restrict__ C,
    float* smf, int bm, int bn)
{
    const uint32_t sb = smem_u32(smf);
    const int tid  = threadIdx.x;
    const int lane = tid & 31;
    const int warp = tid >> 5;
    const int wm_i = warp & 1;
    const int wn_i = warp >> 1;
    const int T = EMB / GKT;   // 32

    auto issue_tile = [&](int t, int buf) {
        const uint32_t base = sb + (uint32_t)buf * (STAGE_FLOATS * 4);
        const float* Ap = A + (size_t)bm * EMB + t * GKT;
        const float* Wp = W + (size_t)bn * EMB + t * GKT;
#pragma unroll
        for (int i = 0; i < 4; i++) {
            int id = tid + i * 256;
            int row = id >> 3;
            int c4 = (id & 7) << 2;
            uint32_t off = (uint32_t)(row * 128 + c4 * 4);
            off ^= (uint32_t)((row & 7) << 4);
            cp16(base + off, Ap + (size_t)row * EMB + c4);
        }
#pragma unroll
        for (int i = 0; i < 4; i++) {
            int id = tid + i * 256;
            int row = id >> 3;
            int c4 = (id & 7) << 2;
            uint32_t off = (uint32_t)(B_OFF_FLOATS * 4 + row * 128 + c4 * 4);
            off ^= (uint32_t)((row & 7) << 4);
            cp16(base + off, Wp + (size_t)row * EMB + c4);
        }
        CP_COMMIT();
    };

    float acc[4][4][4];
#pragma unroll
    for (int mt = 0; mt < 4; mt++)
#pragma unroll
        for (int nt = 0; nt < 4; nt++)
#pragma unroll
            for (int i = 0; i < 4; i++) acc[mt][nt][i] = 0.f;

    issue_tile(0, 0);
    issue_tile(1, 1);

    const int a_rl = ((lane >> 3) & 1) * 8 + (lane & 7);
    const int a_cl = ((lane >> 4) & 1) * 4;
    const int b_rl = lane & 7;
    const int b_cl = ((lane >> 3) & 1) * 4;

    for (int t = 0; t < T; t++) {
        CP_WAIT1();
        __syncthreads();
        if (t + 2 < T) issue_tile(t + 2, (t + 2) % NSTG);
        else CP_COMMIT();

        const uint32_t base  = sb + (uint32_t)(t % NSTG) * (STAGE_FLOATS * 4);
        const uint32_t bbase = base + B_OFF_FLOATS * 4;

#pragma unroll
        for (int kk = 0; kk < 4; kk++) {
            unsigned af[4][4];
#pragma unroll
            for (int mt = 0; mt < 4; mt++) {
                int r = (wm_i * 4 + mt) * 16 + a_rl;
                int cb = kk * 8 + a_cl;
                uint32_t off = (uint32_t)(r * 128 + cb * 4) ^ (uint32_t)((r & 7) << 4);
                ldsm4(af[mt][0], af[mt][1], af[mt][2], af[mt][3], base + off);
            }
            unsigned bf[4][2];
#pragma unroll
            for (int nt = 0; nt < 4; nt++) {
                int n = (wn_i * 4 + nt) * 8 + b_rl;
                int cb = kk * 8 + b_cl;
                uint32_t off = (uint32_t)(n * 128 + cb * 4) ^ (uint32_t)((n & 7) << 4);
                ldsm2(bf[nt][0], bf[nt][1], bbase + off);
            }
#pragma unroll
            for (int mt = 0; mt < 4; mt++)
#pragma unroll
                for (int nt = 0; nt < 4; nt++)
                    mma8(acc[mt][nt], af[mt], bf[nt]);
        }
    }

    const int l3 = lane & 3;
    const int lr = lane >> 2;
#pragma unroll
    for (int mt = 0; mt < 4; mt++) {
        int r0 = bm + wm_i * 64 + mt * 16 + lr;
#pragma unroll
        for (int nt = 0; nt < 4; nt++) {
            int c = bn + wn_i * 32 + nt * 8 + l3 * 2;
            float b0 = __ldg(bias + c), b1 = __ldg(bias + c + 1);
            float v00 = acc[mt][nt][0] + b0, v01 = acc[mt][nt][1] + b1;
            float v10 = acc[mt][nt][2] + b0, v11 = acc[mt][nt][3] + b1;
            if (RND) { v00 = tf32f(v00); v01 = tf32f(v01); v10 = tf32f(v10); v11 = tf32f(v11); }
            *(float2*)(C + (size_t)r0 * EMB + c)       = make_float2(v00, v01);
            *(float2*)(C + (size_t)(r0 + 8) * EMB + c) = make_float2(v10, v11);
        }
    }
}

// batched Q/K/V projection: blockIdx.z selects problem; outputs tf32-rounded
__global__ __launch_bounds__(256, 2) void qkv_gemm_kernel(
    const float* A0, const float* A1, const float* A2,
    const float* W0, const float* W1, const float* W2,
    const float* b0, const float* b1, const float* b2,
    float* C0, float* C1, float* C2)
{
    extern __shared__ float smf[];
    const int z = blockIdx.z;
    const float* A = (z == 0) ? A0 : (z == 1) ? A1 : A2;
    const float* W = (z == 0) ? W0 : (z == 1) ? W1 : W2;
    const float* bias = (z == 0) ? b0 : (z == 1) ? b1 : b2;
    float* C = (z == 0) ? C0 : (z == 1) ? C1 : C2;
    gemm_core<true>(A, W, bias, C, smf, blockIdx.y * 128, blockIdx.x * 128);
}

// single GEMM (output projection, no rounding)
__global__ __launch_bounds__(256, 2) void out_gemm_kernel(
    const float* __restrict__ A, const float* __restrict__ W,
    const float* __restrict__ bias, float* __restrict__ C)
{
    extern __shared__ float smf[];
    gemm_core<false>(A, W, bias, C, smf, blockIdx.y * 128, blockIdx.x * 128);
}

// ============================================================================
// Attention (R11, unchanged): j-block 64 double-buffered, register-resident S.
// ============================================================================
#define AQP 68
#define AKP 68
#define AVP 72
#define KBUF_B (64 * AKP * 4)
#define VBUF_B (64 * AVP * 4)
#define Q_B    (128 * AQP * 4)
#define ATTN_SMEM_BYTES (Q_B + 2 * KBUF_B + 2 * VBUF_B)   // 104 KB

__global__ __launch_bounds__(256, 2) void attn_kernel() {
    extern __shared__ float sm[];
    const uint32_t sb = smem_u32(sm);
    const uint32_t kb0 = sb + Q_B;
    const uint32_t vb0 = sb + Q_B + 2 * KBUF_B;

    const int p = blockIdx.y;
    int rate, off, head, segbase;
    if (p < 24)      { rate = 1; off = 0; segbase = (p / 6) * 2048;         head = p % 6; }
    else if (p < 34) { int q = p - 24; rate = 2; off = 1; segbase = (q / 5) * 4096; head = 6 + q % 5; }
    else             { int q = p - 34; rate = 4; off = 2; segbase = 0;             head = 11 + q; }

    const int tid = threadIdx.x;
    const int lane = tid & 31;
    const int warp = tid >> 5;
    const int l3 = lane & 3;
    const int lr = lane >> 2;
    const int q0 = blockIdx.x * 128;
    const float scale = 0.125f;

    for (int i = tid; i < 2048; i += 256) {
        int s = i >> 4;
        int c4 = (i & 15) << 2;
        int tok = segbase + off + (q0 + s) * rate;
        const float4 v = *(const float4*)(g_q + ((size_t)tok * NH + head) * HD + c4);
        float* d = sm + s * AQP + c4;
        d[0] = v.x * scale; d[1] = v.y * scale;
        d[2] = v.z * scale; d[3] = v.w * scale;
    }

    auto issue_kv = [&](int t, int buf) {
        const uint32_t kd = kb0 + (uint32_t)buf * KBUF_B;
        const uint32_t vd = vb0 + (uint32_t)buf * VBUF_B;
#pragma unroll
        for (int i = 0; i < 4; i++) {
            int id = tid + i * 256;
            int row = id >> 4;
            int cf = (id & 15) << 2;
            int tok = segbase + off + (t * 64 + row) * rate;
            cp16(kd + (uint32_t)((row * AKP + cf) * 4),
                 g_k + ((size_t)tok * NH + head) * HD + cf);
        }
#pragma unroll
        for (int i = 0; i < 4; i++) {
            int id = tid + i * 256;
            int row = id >> 4;
            int cf = (id & 15) << 2;
            int tok = segbase + off + (t * 64 + row) * rate;
            cp16(vd + (uint32_t)((row * AVP + cf) * 4),
                 g_v + ((size_t)tok * NH + head) * HD + cf);
        }
        CP_COMMIT();
    };

    const int a_rl = ((lane >> 3) & 1) * 8 + (lane & 7);
    const int a_cl = ((lane >> 4) & 1) * 4;
    const int b_rl = lane & 7;
    const int b_cl = ((lane >> 3) & 1) * 4;
    const int srcA = (lane & ~3) | (l3 >> 1);
    const int srcB = srcA + 2;
    const bool odd = (l3 & 1);

    float o[8][4];
#pragma unroll
    for (int nt = 0; nt < 8; nt++) { o[nt][0] = o[nt][1] = o[nt][2] = o[nt][3] = 0.f; }
    float m0 = -1e30f, m1 = -1e30f, l0 = 0.f, l1 = 0.f;

    issue_kv(0, 0);

    const int T = 2048 / 64;
    for (int t = 0; t < T; t++) {
        if (t + 1 < T) { issue_kv(t + 1, (t + 1) & 1); CP_WAIT1(); }
        else           { CP_WAIT0(); }
        __syncthreads();

        const uint32_t kd = kb0 + (uint32_t)(t & 1) * KBUF_B;
        const float* Vsb = sm + (Q_B + 2 * KBUF_B + (t & 1) * VBUF_B) / 4;

        float s[8][4];
#pragma unroll
        for (int nt = 0; nt < 8; nt++) { s[nt][0] = s[nt][1] = s[nt][2] = s[nt][3] = 0.f; }
#pragma unroll
        for (int kk = 0; kk < 8; kk++) {
            unsigned qa[4];
            {
                int r = warp * 16 + a_rl;
                ldsm4(qa[0], qa[1], qa[2], qa[3],
                      sb + (uint32_t)((r * AQP + kk * 8 + a_cl) * 4));
            }
#pragma unroll
            for (int nt = 0; nt < 8; nt++) {
                int n = nt * 8 + b_rl;
                unsigned kbr[2];
                ldsm2(kbr[0], kbr[1], kd + (uint32_t)((n * AKP + kk * 8 + b_cl) * 4));
                mma8(s[nt], qa, kbr);
            }
        }
        float mx0 = -1e30f, mx1 = -1e30f;
#pragma unroll
        for (int nt = 0; nt < 8; nt++) {
            mx0 = fmaxf(mx0, fmaxf(s[nt][0], s[nt][1]));
            mx1 = fmaxf(mx1, fmaxf(s[nt][2], s[nt][3]));
        }
        mx0 = fmaxf(mx0, __shfl_xor_sync(0xffffffffu, mx0, 1));
        mx0 = fmaxf(mx0, __shfl_xor_sync(0xffffffffu, mx0, 2));
        mx1 = fmaxf(mx1, __shfl_xor_sync(0xffffffffu, mx1, 1));
        mx1 = fmaxf(mx1, __shfl_xor_sync(0xffffffffu, mx1, 2));
        float mn0 = fmaxf(m0, mx0), mn1 = fmaxf(m1, mx1);
        float al0 = __expf(m0 - mn0), al1 = __expf(m1 - mn1);
#pragma unroll
        for (int nt = 0; nt < 8; nt++) {
            o[nt][0] *= al0; o[nt][1] *= al0; o[nt][2] *= al1; o[nt][3] *= al1;
        }
        float sum0 = 0.f, sum1 = 0.f;
#pragma unroll
        for (int nt = 0; nt < 8; nt++) {
            float e0 = __expf(s[nt][0] - mn0); sum0 += e0; s[nt][0] = tf32f(e0);
            float e1 = __expf(s[nt][1] - mn0); sum0 += e1; s[nt][1] = tf32f(e1);
            float e2 = __expf(s[nt][2] - mn1); sum1 += e2; s[nt][2] = tf32f(e2);
            float e3 = __expf(s[nt][3] - mn1); sum1 += e3; s[nt][3] = tf32f(e3);
        }
        sum0 += __shfl_xor_sync(0xffffffffu, sum0, 1);
        sum0 += __shfl_xor_sync(0xffffffffu, sum0, 2);
        sum1 += __shfl_xor_sync(0xffffffffu, sum1, 1);
        sum1 += __shfl_xor_sync(0xffffffffu, sum1, 2);
        l0 = l0 * al0 + sum0;
        l1 = l1 * al1 + sum1;
        m0 = mn0; m1 = mn1;

#pragma unroll
        for (int kk = 0; kk < 8; kk++) {
            unsigned a[4];
            {
                float u, v;
                u = __shfl_sync(0xffffffffu, s[kk][0], srcA);
                v = __shfl_sync(0xffffffffu, s[kk][1], srcA);
                a[0] = fbits(odd ? v : u);
                u = __shfl_sync(0xffffffffu, s[kk][2], srcA);
                v = __shfl_sync(0xffffffffu, s[kk][3], srcA);
                a[1] = fbits(odd ? v : u);
                u = __shfl_sync(0xffffffffu, s[kk][0], srcB);
                v = __shfl_sync(0xffffffffu, s[kk][1], srcB);
                a[2] = fbits(odd ? v : u);
                u = __shfl_sync(0xffffffffu, s[kk][2], srcB);
                v = __shfl_sync(0xffffffffu, s[kk][3], srcB);
                a[3] = fbits(odd ? v : u);
            }
            const int kr = kk * 8 + l3;
#pragma unroll
            for (int nto = 0; nto < 8; nto++) {
                unsigned b[2];
                b[0] = fbits(Vsb[kr * AVP + nto * 8 + lr]);
                b[1] = fbits(Vsb[(kr + 4) * AVP + nto * 8 + lr]);
                mma8(o[nto], a, b);
            }
        }
        __syncthreads();
    }

    {
        float inv0 = 1.f / l0;
        float inv1 = 1.f / l1;
        int tok0 = segbase + off + (q0 + warp * 16 + lr) * rate;
        int tok1 = segbase + off + (q0 + warp * 16 + lr + 8) * rate;
#pragma unroll
        for (int nt = 0; nt < 8; nt++) {
            int c = nt * 8 + (l3 << 1);
            *(float2*)(g_x + ((size_t)tok0 * NH + head) * HD + c) =
                make_float2(o[nt][0] * inv0, o[nt][1] * inv0);
            *(float2*)(g_x + ((size_t)tok1 * NH + head) * HD + c) =
                make_float2(o[nt][2] * inv1, o[nt][3] * inv1);
        }
    }
}

// ---------------- LayerNorm (writes tf32-pre-rounded output) ----------------
__global__ __launch_bounds__(256) void ln_kernel(
    const float* __restrict__ x_in, float* __restrict__ y_out,
    const float* __restrict__ gam, const float* __restrict__ bet)
{
    __shared__ float red[16];
    const int row = blockIdx.x;
    const int tid = threadIdx.x;
    const int c = tid * 4;
    const float4 xv = *(const float4*)(x_in + (size_t)row * EMB + c);
    float s = xv.x + xv.y + xv.z + xv.w;
    float s2 = xv.x * xv.x + xv.y * xv.y + xv.z * xv.z + xv.w * xv.w;
#pragma unroll
    for (int o = 16; o; o >>= 1) {
        s += __shfl_xor_sync(0xffffffffu, s, o);
        s2 += __shfl_xor_sync(0xffffffffu, s2, o);
    }
    if ((tid & 31) == 0) { red[tid >> 5] = s; red[8 + (tid >> 5)] = s2; }
    __syncthreads();
    if (tid < 32) {
        float a = (tid < 8) ? red[tid] : 0.f;
        float b = (tid < 8) ? red[8 + tid] : 0.f;
#pragma unroll
        for (int o = 4; o; o >>= 1) {
            a += __shfl_xor_sync(0xffffffffu, a, o);
            b += __shfl_xor_sync(0xffffffffu, b, o);
        }
        if (tid == 0) { red[0] = a; red[1] = b; }
    }
    __syncthreads();
    const float mu = red[0] * (1.f / EMB);
    const float var = red[1] * (1.f / EMB) - mu * mu;
    const float rs = rsqrtf(var + 1e-5f);
    const float4 gv = *(const float4*)(gam + c);
    const float4 bv = *(const float4*)(bet + c);
    float4 ov;
    ov.x = tf32f((xv.x - mu) * rs * gv.x + bv.x);
    ov.y = tf32f((xv.y - mu) * rs * gv.y + bv.y);
    ov.z = tf32f((xv.z - mu) * rs * gv.z + bv.z);
    ov.w = tf32f((xv.w - mu) * rs * gv.w + bv.w);
    *(float4*)(y_out + (size_t)row * EMB + c) = ov;
}

// ---------------- launch ----------------
extern "C" void kernel_launch(void* const* d_in, const int* in_sizes, int n_in,
                              void* d_out, int out_size)
{
    (void)in_sizes; (void)n_in; (void)out_size;
    const float* query = (const float*)d_in[0];
    const float* key   = (const float*)d_in[1];
    const float* value = (const float*)d_in[2];
    const float* Wq = (const float*)d_in[3];
    const float* bq = (const float*)d_in[4];
    const float* Wk = (const float*)d_in[5];
    const float* bk = (const float*)d_in[6];
    const float* Wv = (const float*)d_in[7];
    const float* bv = (const float*)d_in[8];
    const float* Wo = (const float*)d_in[9];
    const float* bo = (const float*)d_in[10];
    const float* ln_g = (const float*)d_in[11];
    const float* ln_b = (const float*)d_in[12];
    float* out = (float*)d_out;

    float *pq, *pk, *pv, *px, *pln, *pqi, *pki, *pvi, *pwq, *pwk, *pwv, *pwo;
    cudaGetSymbolAddress((void**)&pq, g_q);
    cudaGetSymbolAddress((void**)&pk, g_k);
    cudaGetSymbolAddress((void**)&pv, g_v);
    cudaGetSymbolAddress((void**)&px, g_x);
    cudaGetSymbolAddress((void**)&pln, g_ln);
    cudaGetSymbolAddress((void**)&pqi, g_qi);
    cudaGetSymbolAddress((void**)&pki, g_ki);
    cudaGetSymbolAddress((void**)&pvi, g_vi);
    cudaGetSymbolAddress((void**)&pwq, g_wq);
    cudaGetSymbolAddress((void**)&pwk, g_wk);
    cudaGetSymbolAddress((void**)&pwv, g_wv);
    cudaGetSymbolAddress((void**)&pwo, g_wo);

    prep_kernel<<<PREP_BLOCKS, 256>>>(
        (const float4*)query, (const float4*)key, (const float4*)value,
        (const float4*)Wq, (const float4*)Wk, (const float4*)Wv, (const float4*)Wo,
        (float4*)px, (float4*)pqi, (float4*)pki, (float4*)pvi,
        (float4*)pwq, (float4*)pwk, (float4*)pwv, (float4*)pwo);

    cudaFuncSetAttribute(qkv_gemm_kernel,
                         cudaFuncAttributeMaxDynamicSharedMemorySize, GEMM_SMEM_BYTES);
    cudaFuncSetAttribute(out_gemm_kernel,
                         cudaFuncAttributeMaxDynamicSharedMemorySize, GEMM_SMEM_BYTES);

    qkv_gemm_kernel<<<dim3(EMB / 128, NTOK / 128, 3), 256, GEMM_SMEM_BYTES>>>(
        pqi, pki, pvi, pwq, pwk, pwv, bq, bk, bv, pq, pk, pv);

    cudaFuncSetAttribute(attn_kernel, cudaFuncAttributeMaxDynamicSharedMemorySize,
                         ATTN_SMEM_BYTES);
    attn_kernel<<<dim3(16, 39), 256, ATTN_SMEM_BYTES>>>();

    ln_kernel<<<NTOK, 256>>>(px, pln, ln_g, ln_b);

    out_gemm_kernel<<<dim3(EMB / 128, NTOK / 128), 256, GEMM_SMEM_BYTES>>>(
        pln, pwo, bo, out);
}

// round 15
// speedup vs baseline: 2.1578x; 1.0309x over previous
#include <cuda_runtime.h>
#include <stdint.h>
#include <stddef.h>

#define NTOK 8192
#define EMB  1024
#define NH   16
#define HD   64

// ---------------- scratch (static device globals; no allocation) ----------------
__device__ float g_q[(size_t)NTOK * EMB];
__device__ float g_k[(size_t)NTOK * EMB];
__device__ float g_v[(size_t)NTOK * EMB];
__device__ float g_x[(size_t)NTOK * EMB];
__device__ float g_ln[(size_t)NTOK * EMB];
__device__ float g_qi[(size_t)NTOK * EMB];
__device__ float g_ki[(size_t)NTOK * EMB];
__device__ float g_vi[(size_t)NTOK * EMB];
__device__ float g_wq[(size_t)EMB * EMB];
__device__ float g_wk[(size_t)EMB * EMB];
__device__ float g_wv[(size_t)EMB * EMB];
__device__ float g_wo[(size_t)EMB * EMB];

// ---------------- helpers ----------------
__device__ __forceinline__ float tf32f(float x) {
    unsigned u;
    asm("cvt.rna.tf32.f32 %0, %1;" : "=r"(u) : "f"(x));
    return __uint_as_float(u);
}
__device__ __forceinline__ unsigned fbits(float x) { return __float_as_uint(x); }

__device__ __forceinline__ uint32_t smem_u32(const void* p) {
    uint32_t a;
    asm("{ .reg .u64 t; cvta.to.shared.u64 t, %1; cvt.u32.u64 %0, t; }" : "=r"(a) : "l"(p));
    return a;
}

__device__ __forceinline__ void cp16(uint32_t dst, const void* src) {
    asm volatile("cp.async.cg.shared.global [%0], [%1], 16;" :: "r"(dst), "l"(src));
}
#define CP_COMMIT() asm volatile("cp.async.commit_group;" ::: "memory")
#define CP_WAIT1()  asm volatile("cp.async.wait_group 1;" ::: "memory")
#define CP_WAIT0()  asm volatile("cp.async.wait_group 0;" ::: "memory")

__device__ __forceinline__ void ldsm4(unsigned& r0, unsigned& r1, unsigned& r2, unsigned& r3,
                                      uint32_t addr) {
    asm volatile("ldmatrix.sync.aligned.m8n8.x4.shared.b16 {%0,%1,%2,%3}, [%4];"
                 : "=r"(r0), "=r"(r1), "=r"(r2), "=r"(r3) : "r"(addr));
}

__device__ __forceinline__ void mma8(float c[4], const unsigned a[4], const unsigned b[2]) {
    asm volatile(
        "mma.sync.aligned.m16n8k8.row.col.f32.tf32.tf32.f32 "
        "{%0,%1,%2,%3},{%4,%5,%6,%7},{%8,%9},{%0,%1,%2,%3};\n"
        : "+f"(c[0]), "+f"(c[1]), "+f"(c[2]), "+f"(c[3])
        : "r"(a[0]), "r"(a[1]), "r"(a[2]), "r"(a[3]), "r"(b[0]), "r"(b[1]));
}

// ---------------- fused preamble: zero g_x + round inputs/weights ----------------
#define SEG4  (NTOK * EMB / 4)
#define WSEG4 (EMB * EMB / 4)
#define PREP_TOTAL4 (4 * SEG4 + 4 * WSEG4)
#define PREP_BLOCKS (PREP_TOTAL4 / 256)

__global__ void prep_kernel(const float4* __restrict__ q, const float4* __restrict__ k,
                            const float4* __restrict__ v,
                            const float4* __restrict__ wq, const float4* __restrict__ wk,
                            const float4* __restrict__ wv, const float4* __restrict__ wo,
                            float4* __restrict__ x0,
                            float4* __restrict__ qi, float4* __restrict__ ki,
                            float4* __restrict__ vi,
                            float4* __restrict__ owq, float4* __restrict__ owk,
                            float4* __restrict__ owv, float4* __restrict__ owo)
{
    size_t i = (size_t)blockIdx.x * 256 + threadIdx.x;
    if (i < SEG4) { x0[i] = make_float4(0.f, 0.f, 0.f, 0.f); return; }
    i -= SEG4;
    const float4* src;
    float4* dst;
    if (i < 3 * (size_t)SEG4) {
        size_t s = i / SEG4;
        i -= s * SEG4;
        src = (s == 0) ? q : (s == 1) ? k : v;
        dst = (s == 0) ? qi : (s == 1) ? ki : vi;
    } else {
        i -= 3 * (size_t)SEG4;
        size_t s = i / WSEG4;
        i -= s * WSEG4;
        src = (s == 0) ? wq : (s == 1) ? wk : (s == 2) ? wv : wo;
        dst = (s == 0) ? owq : (s == 1) ? owk : (s == 2) ? owv : owo;
    }
    float4 val = src[i];
    dst[i] = make_float4(tf32f(val.x), tf32f(val.y), tf32f(val.z), tf32f(val.w));
}

// ============================================================================
// GEMM core: operands pre-rounded tf32. CTA 128x128, 8 warps 2x4, warp 64x32,
// KT=32, 3-stage cp.async, 2 CTA/SM. B-fragments via paired ldsm4 (2 frags/op).
// ============================================================================
#define GKT 32
#define NSTG 3
#define STAGE_FLOATS (2 * 128 * GKT)
#define B_OFF_FLOATS (128 * GKT)
#define GEMM_SMEM_BYTES (NSTG * STAGE_FLOATS * 4)

template <bool RND>
__device__ __forceinline__ void gemm_core(
    const float* __restrict__ A, const float* __restrict__ W,
    const float* __restrict__ bias, float* __restrict__ C,
    float* smf, int bm, int bn)
{
    const uint32_t sb = smem_u32(smf);
    const int tid  = threadIdx.x;
    const int lane = tid & 31;
    const int warp = tid >> 5;
    const int wm_i = warp & 1;
    const int wn_i = warp >> 1;
    const int T = EMB / GKT;   // 32

    auto issue_tile = [&](int t, int buf) {
        const uint32_t base = sb + (uint32_t)buf * (STAGE_FLOATS * 4);
        const float* Ap = A + (size_t)bm * EMB + t * GKT;
        const float* Wp = W + (size_t)bn * EMB + t * GKT;
#pragma unroll
        for (int i = 0; i < 4; i++) {
            int id = tid + i * 256;
            int row = id >> 3;
            int c4 = (id & 7) << 2;
            uint32_t off = (uint32_t)(row * 128 + c4 * 4);
            off ^= (uint32_t)((row & 7) << 4);
            cp16(base + off, Ap + (size_t)row * EMB + c4);
        }
#pragma unroll
        for (int i = 0; i < 4; i++) {
            int id = tid + i * 256;
            int row = id >> 3;
            int c4 = (id & 7) << 2;
            uint32_t off = (uint32_t)(B_OFF_FLOATS * 4 + row * 128 + c4 * 4);
            off ^= (uint32_t)((row & 7) << 4);
            cp16(base + off, Wp + (size_t)row * EMB + c4);
        }
        CP_COMMIT();
    };

    float acc[4][4][4];
#pragma unroll
    for (int mt = 0; mt < 4; mt++)
#pragma unroll
        for (int nt = 0; nt < 4; nt++)
#pragma unroll
            for (int i = 0; i < 4; i++) acc[mt][nt][i] = 0.f;

    issue_tile(0, 0);
    issue_tile(1, 1);

    // A x4: row-bit = lane>>3, col-bit = lane>>4 -> regs a0..a3
    const int a_rl = ((lane >> 3) & 1) * 8 + (lane & 7);
    const int a_cl = ((lane >> 4) & 1) * 4;
    // B paired x4: row-bit = lane>>4, col-bit = lane>>3 -> regs = {b0,b1}even,{b0,b1}odd
    const int bx_rl = (lane & 7) + (((lane >> 4) & 1) << 3);
    const int bx_cl = ((lane >> 3) & 1) * 4;

    for (int t = 0; t < T; t++) {
        CP_WAIT1();
        __syncthreads();
        if (t + 2 < T) issue_tile(t + 2, (t + 2) % NSTG);
        else CP_COMMIT();

        const uint32_t base  = sb + (uint32_t)(t % NSTG) * (STAGE_FLOATS * 4);
        const uint32_t bbase = base + B_OFF_FLOATS * 4;

#pragma unroll
        for (int kk = 0; kk < 4; kk++) {
            unsigned af[4][4];
#pragma unroll
            for (int mt = 0; mt < 4; mt++) {
                int r = (wm_i * 4 + mt) * 16 + a_rl;
                int cb = kk * 8 + a_cl;
                uint32_t off = (uint32_t)(r * 128 + cb * 4) ^ (uint32_t)((r & 7) << 4);
                ldsm4(af[mt][0], af[mt][1], af[mt][2], af[mt][3], base + off);
            }
            unsigned bf[4][2];
#pragma unroll
            for (int ntp = 0; ntp < 2; ntp++) {
                int n = (wn_i * 4 + ntp * 2) * 8 + bx_rl;
                int cb = kk * 8 + bx_cl;
                uint32_t off = (uint32_t)(n * 128 + cb * 4) ^ (uint32_t)((n & 7) << 4);
                ldsm4(bf[2 * ntp][0], bf[2 * ntp][1], bf[2 * ntp + 1][0], bf[2 * ntp + 1][1],
                      bbase + off);
            }
#pragma unroll
            for (int mt = 0; mt < 4; mt++)
#pragma unroll
                for (int nt = 0; nt < 4; nt++)
                    mma8(acc[mt][nt], af[mt], bf[nt]);
        }
    }

    const int l3 = lane & 3;
    const int lr = lane >> 2;
#pragma unroll
    for (int mt = 0; mt < 4; mt++) {
        int r0 = bm + wm_i * 64 + mt * 16 + lr;
#pragma unroll
        for (int nt = 0; nt < 4; nt++) {
            int c = bn + wn_i * 32 + nt * 8 + l3 * 2;
            float b0 = __ldg(bias + c), b1 = __ldg(bias + c + 1);
            float v00 = acc[mt][nt][0] + b0, v01 = acc[mt][nt][1] + b1;
            float v10 = acc[mt][nt][2] + b0, v11 = acc[mt][nt][3] + b1;
            if (RND) { v00 = tf32f(v00); v01 = tf32f(v01); v10 = tf32f(v10); v11 = tf32f(v11); }
            *(float2*)(C + (size_t)r0 * EMB + c)       = make_float2(v00, v01);
            *(float2*)(C + (size_t)(r0 + 8) * EMB + c) = make_float2(v10, v11);
        }
    }
}

__global__ __launch_bounds__(256, 2) void qkv_gemm_kernel(
    const float* A0, const float* A1, const float* A2,
    const float* W0, const float* W1, const float* W2,
    const float* b0, const float* b1, const float* b2,
    float* C0, float* C1, float* C2)
{
    extern __shared__ float smf[];
    const int z = blockIdx.z;
    const float* A = (z == 0) ? A0 : (z == 1) ? A1 : A2;
    const float* W = (z == 0) ? W0 : (z == 1) ? W1 : W2;
    const float* bias = (z == 0) ? b0 : (z == 1) ? b1 : b2;
    float* C = (z == 0) ? C0 : (z == 1) ? C1 : C2;
    gemm_core<true>(A, W, bias, C, smf, blockIdx.y * 128, blockIdx.x * 128);
}

__global__ __launch_bounds__(256, 2) void out_gemm_kernel(
    const float* __restrict__ A, const float* __restrict__ W,
    const float* __restrict__ bias, float* __restrict__ C)
{
    extern __shared__ float smf[];
    gemm_core<false>(A, W, bias, C, smf, blockIdx.y * 128, blockIdx.x * 128);
}

// ============================================================================
// Attention: j-block 64 double-buffered, register-resident S, in-warp softmax.
// K-fragments via paired ldsm4 (2 frags/op).
// ============================================================================
#define AQP 68
#define AKP 68
#define AVP 72
#define KBUF_B (64 * AKP * 4)
#define VBUF_B (64 * AVP * 4)
#define Q_B    (128 * AQP * 4)
#define ATTN_SMEM_BYTES (Q_B + 2 * KBUF_B + 2 * VBUF_B)   // 104 KB

__global__ __launch_bounds__(256, 2) void attn_kernel() {
    extern __shared__ float sm[];
    const uint32_t sb = smem_u32(sm);
    const uint32_t kb0 = sb + Q_B;
    const uint32_t vb0 = sb + Q_B + 2 * KBUF_B;

    const int p = blockIdx.y;
    int rate, off, head, segbase;
    if (p < 24)      { rate = 1; off = 0; segbase = (p / 6) * 2048;         head = p % 6; }
    else if (p < 34) { int q = p - 24; rate = 2; off = 1; segbase = (q / 5) * 4096; head = 6 + q % 5; }
    else             { int q = p - 34; rate = 4; off = 2; segbase = 0;             head = 11 + q; }

    const int tid = threadIdx.x;
    const int lane = tid & 31;
    const int warp = tid >> 5;
    const int l3 = lane & 3;
    const int lr = lane >> 2;
    const int q0 = blockIdx.x * 128;
    const float scale = 0.125f;

    for (int i = tid; i < 2048; i += 256) {
        int s = i >> 4;
        int c4 = (i & 15) << 2;
        int tok = segbase + off + (q0 + s) * rate;
        const float4 v = *(const float4*)(g_q + ((size_t)tok * NH + head) * HD + c4);
        float* d = sm + s * AQP + c4;
        d[0] = v.x * scale; d[1] = v.y * scale;
        d[2] = v.z * scale; d[3] = v.w * scale;
    }

    auto issue_kv = [&](int t, int buf) {
        const uint32_t kd = kb0 + (uint32_t)buf * KBUF_B;
        const uint32_t vd = vb0 + (uint32_t)buf * VBUF_B;
#pragma unroll
        for (int i = 0; i < 4; i++) {
            int id = tid + i * 256;
            int row = id >> 4;
            int cf = (id & 15) << 2;
            int tok = segbase + off + (t * 64 + row) * rate;
            cp16(kd + (uint32_t)((row * AKP + cf) * 4),
                 g_k + ((size_t)tok * NH + head) * HD + cf);
        }
#pragma unroll
        for (int i = 0; i < 4; i++) {
            int id = tid + i * 256;
            int row = id >> 4;
            int cf = (id & 15) << 2;
            int tok = segbase + off + (t * 64 + row) * rate;
            cp16(vd + (uint32_t)((row * AVP + cf) * 4),
                 g_v + ((size_t)tok * NH + head) * HD + cf);
        }
        CP_COMMIT();
    };

    const int a_rl = ((lane >> 3) & 1) * 8 + (lane & 7);
    const int a_cl = ((lane >> 4) & 1) * 4;
    const int bx_rl = (lane & 7) + (((lane >> 4) & 1) << 3);
    const int bx_cl = ((lane >> 3) & 1) * 4;
    const int srcA = (lane & ~3) | (l3 >> 1);
    const int srcB = srcA + 2;
    const bool odd = (l3 & 1);

    float o[8][4];
#pragma unroll
    for (int nt = 0; nt < 8; nt++) { o[nt][0] = o[nt][1] = o[nt][2] = o[nt][3] = 0.f; }
    float m0 = -1e30f, m1 = -1e30f, l0 = 0.f, l1 = 0.f;

    issue_kv(0, 0);

    const int T = 2048 / 64;
    for (int t = 0; t < T; t++) {
        if (t + 1 < T) { issue_kv(t + 1, (t + 1) & 1); CP_WAIT1(); }
        else           { CP_WAIT0(); }
        __syncthreads();

        const uint32_t kd = kb0 + (uint32_t)(t & 1) * KBUF_B;
        const float* Vsb = sm + (Q_B + 2 * KBUF_B + (t & 1) * VBUF_B) / 4;

        float s[8][4];
#pragma unroll
        for (int nt = 0; nt < 8; nt++) { s[nt][0] = s[nt][1] = s[nt][2] = s[nt][3] = 0.f; }
#pragma unroll
        for (int kk = 0; kk < 8; kk++) {
            unsigned qa[4];
            {
                int r = warp * 16 + a_rl;
                ldsm4(qa[0], qa[1], qa[2], qa[3],
                      sb + (uint32_t)((r * AQP + kk * 8 + a_cl) * 4));
            }
            unsigned kb[8][2];
#pragma unroll
            for (int ntp = 0; ntp < 4; ntp++) {
                int n = ntp * 16 + bx_rl;
                ldsm4(kb[2 * ntp][0], kb[2 * ntp][1], kb[2 * ntp + 1][0], kb[2 * ntp + 1][1],
                      kd + (uint32_t)((n * AKP + kk * 8 + bx_cl) * 4));
            }
#pragma unroll
            for (int nt = 0; nt < 8; nt++)
                mma8(s[nt], qa, kb[nt]);
        }
        float mx0 = -1e30f, mx1 = -1e30f;
#pragma unroll
        for (int nt = 0; nt < 8; nt++) {
            mx0 = fmaxf(mx0, fmaxf(s[nt][0], s[nt][1]));
            mx1 = fmaxf(mx1, fmaxf(s[nt][2], s[nt][3]));
        }
        mx0 = fmaxf(mx0, __shfl_xor_sync(0xffffffffu, mx0, 1));
        mx0 = fmaxf(mx0, __shfl_xor_sync(0xffffffffu, mx0, 2));
        mx1 = fmaxf(mx1, __shfl_xor_sync(0xffffffffu, mx1, 1));
        mx1 = fmaxf(mx1, __shfl_xor_sync(0xffffffffu, mx1, 2));
        float mn0 = fmaxf(m0, mx0), mn1 = fmaxf(m1, mx1);
        float al0 = __expf(m0 - mn0), al1 = __expf(m1 - mn1);
#pragma unroll
        for (int nt = 0; nt < 8; nt++) {
            o[nt][0] *= al0; o[nt][1] *= al0; o[nt][2] *= al1; o[nt][3] *= al1;
        }
        float sum0 = 0.f, sum1 = 0.f;
#pragma unroll
        for (int nt = 0; nt < 8; nt++) {
            float e0 = __expf(s[nt][0] - mn0); sum0 += e0; s[nt][0] = tf32f(e0);
            float e1 = __expf(s[nt][1] - mn0); sum0 += e1; s[nt][1] = tf32f(e1);
            float e2 = __expf(s[nt][2] - mn1); sum1 += e2; s[nt][2] = tf32f(e2);
            float e3 = __expf(s[nt][3] - mn1); sum1 += e3; s[nt][3] = tf32f(e3);
        }
        sum0 += __shfl_xor_sync(0xffffffffu, sum0, 1);
        sum0 += __shfl_xor_sync(0xffffffffu, sum0, 2);
        sum1 += __shfl_xor_sync(0xffffffffu, sum1, 1);
        sum1 += __shfl_xor_sync(0xffffffffu, sum1, 2);
        l0 = l0 * al0 + sum0;
        l1 = l1 * al1 + sum1;
        m0 = mn0; m1 = mn1;

#pragma unroll
        for (int kk = 0; kk < 8; kk++) {
            unsigned a[4];
            {
                float u, v;
                u = __shfl_sync(0xffffffffu, s[kk][0], srcA);
                v = __shfl_sync(0xffffffffu, s[kk][1], srcA);
                a[0] = fbits(odd ? v : u);
                u = __shfl_sync(0xffffffffu, s[kk][2], srcA);
                v = __shfl_sync(0xffffffffu, s[kk][3], srcA);
                a[1] = fbits(odd ? v : u);
                u = __shfl_sync(0xffffffffu, s[kk][0], srcB);
                v = __shfl_sync(0xffffffffu, s[kk][1], srcB);
                a[2] = fbits(odd ? v : u);
                u = __shfl_sync(0xffffffffu, s[kk][2], srcB);
                v = __shfl_sync(0xffffffffu, s[kk][3], srcB);
                a[3] = fbits(odd ? v : u);
            }
            const int kr = kk * 8 + l3;
#pragma unroll
            for (int nto = 0; nto < 8; nto++) {
                unsigned b[2];
                b[0] = fbits(Vsb[kr * AVP + nto * 8 + lr]);
                b[1] = fbits(Vsb[(kr + 4) * AVP + nto * 8 + lr]);
                mma8(o[nto], a, b);
            }
        }
        __syncthreads();
    }

    {
        float inv0 = 1.f / l0;
        float inv1 = 1.f / l1;
        int tok0 = segbase + off + (q0 + warp * 16 + lr) * rate;
        int tok1 = segbase + off + (q0 + warp * 16 + lr + 8) * rate;
#pragma unroll
        for (int nt = 0; nt < 8; nt++) {
            int c = nt * 8 + (l3 << 1);
            *(float2*)(g_x + ((size_t)tok0 * NH + head) * HD + c) =
                make_float2(o[nt][0] * inv0, o[nt][1] * inv0);
            *(float2*)(g_x + ((size_t)tok1 * NH + head) * HD + c) =
                make_float2(o[nt][2] * inv1, o[nt][3] * inv1);
        }
    }
}

// ---------------- LayerNorm (writes tf32-pre-rounded output) ----------------
__global__ __launch_bounds__(256) void ln_kernel(
    const float* __restrict__ x_in, float* __restrict__ y_out,
    const float* __restrict__ gam, const float* __restrict__ bet)
{
    __shared__ float red[16];
    const int row = blockIdx.x;
    const int tid = threadIdx.x;
    const int c = tid * 4;
    const float4 xv = *(const float4*)(x_in + (size_t)row * EMB + c);
    float s = xv.x + xv.y + xv.z + xv.w;
    float s2 = xv.x * xv.x + xv.y * xv.y + xv.z * xv.z + xv.w * xv.w;
#pragma unroll
    for (int o = 16; o; o >>= 1) {
        s += __shfl_xor_sync(0xffffffffu, s, o);
        s2 += __shfl_xor_sync(0xffffffffu, s2, o);
    }
    if ((tid & 31) == 0) { red[tid >> 5] = s; red[8 + (tid >> 5)] = s2; }
    __syncthreads();
    if (tid < 32) {
        float a = (tid < 8) ? red[tid] : 0.f;
        float b = (tid < 8) ? red[8 + tid] : 0.f;
#pragma unroll
        for (int o = 4; o; o >>= 1) {
            a += __shfl_xor_sync(0xffffffffu, a, o);
            b += __shfl_xor_sync(0xffffffffu, b, o);
        }
        if (tid == 0) { red[0] = a; red[1] = b; }
    }
    __syncthreads();
    const float mu = red[0] * (1.f / EMB);
    const float var = red[1] * (1.f / EMB) - mu * mu;
    const float rs = rsqrtf(var + 1e-5f);
    const float4 gv = *(const float4*)(gam + c);
    const float4 bv = *(const float4*)(bet + c);
    float4 ov;
    ov.x = tf32f((xv.x - mu) * rs * gv.x + bv.x);
    ov.y = tf32f((xv.y - mu) * rs * gv.y + bv.y);
    ov.z = tf32f((xv.z - mu) * rs * gv.z + bv.z);
    ov.w = tf32f((xv.w - mu) * rs * gv.w + bv.w);
    *(float4*)(y_out + (size_t)row * EMB + c) = ov;
}

// ---------------- launch ----------------
extern "C" void kernel_launch(void* const* d_in, const int* in_sizes, int n_in,
                              void* d_out, int out_size)
{
    (void)in_sizes; (void)n_in; (void)out_size;
    const float* query = (const float*)d_in[0];
    const float* key   = (const float*)d_in[1];
    const float* value = (const float*)d_in[2];
    const float* Wq = (const float*)d_in[3];
    const float* bq = (const float*)d_in[4];
    const float* Wk = (const float*)d_in[5];
    const float* bk = (const float*)d_in[6];
    const float* Wv = (const float*)d_in[7];
    const float* bv = (const float*)d_in[8];
    const float* Wo = (const float*)d_in[9];
    const float* bo = (const float*)d_in[10];
    const float* ln_g = (const float*)d_in[11];
    const float* ln_b = (const float*)d_in[12];
    float* out = (float*)d_out;

    float *pq, *pk, *pv, *px, *pln, *pqi, *pki, *pvi, *pwq, *pwk, *pwv, *pwo;
    cudaGetSymbolAddress((void**)&pq, g_q);
    cudaGetSymbolAddress((void**)&pk, g_k);
    cudaGetSymbolAddress((void**)&pv, g_v);
    cudaGetSymbolAddress((void**)&px, g_x);
    cudaGetSymbolAddress((void**)&pln, g_ln);
    cudaGetSymbolAddress((void**)&pqi, g_qi);
    cudaGetSymbolAddress((void**)&pki, g_ki);
    cudaGetSymbolAddress((void**)&pvi, g_vi);
    cudaGetSymbolAddress((void**)&pwq, g_wq);
    cudaGetSymbolAddress((void**)&pwk, g_wk);
    cudaGetSymbolAddress((void**)&pwv, g_wv);
    cudaGetSymbolAddress((void**)&pwo, g_wo);

    prep_kernel<<<PREP_BLOCKS, 256>>>(
        (const float4*)query, (const float4*)key, (const float4*)value,
        (const float4*)Wq, (const float4*)Wk, (const float4*)Wv, (const float4*)Wo,
        (float4*)px, (float4*)pqi, (float4*)pki, (float4*)pvi,
        (float4*)pwq, (float4*)pwk, (float4*)pwv, (float4*)pwo);

    cudaFuncSetAttribute(qkv_gemm_kernel,
                         cudaFuncAttributeMaxDynamicSharedMemorySize, GEMM_SMEM_BYTES);
    cudaFuncSetAttribute(out_gemm_kernel,
                         cudaFuncAttributeMaxDynamicSharedMemorySize, GEMM_SMEM_BYTES);

    qkv_gemm_kernel<<<dim3(EMB / 128, NTOK / 128, 3), 256, GEMM_SMEM_BYTES>>>(
        pqi, pki, pvi, pwq, pwk, pwv, bq, bk, bv, pq, pk, pv);

    cudaFuncSetAttribute(attn_kernel, cudaFuncAttributeMaxDynamicSharedMemorySize,
                         ATTN_SMEM_BYTES);
    attn_kernel<<<dim3(16, 39), 256, ATTN_SMEM_BYTES>>>();

    ln_kernel<<<NTOK, 256>>>(px, pln, ln_g, ln_b);

    out_gemm_kernel<<<dim3(EMB / 128, NTOK / 128), 256, GEMM_SMEM_BYTES>>>(
        pln, pwo, bo, out);
}

// round 17
// speedup vs baseline: 2.1783x; 1.0095x over previous
#include <cuda_runtime.h>
#include <stdint.h>
#include <stddef.h>

#define NTOK 8192
#define EMB  1024
#define NH   16
#define HD   64

// ---------------- scratch (static device globals; no allocation) ----------------
__device__ float g_q[(size_t)NTOK * EMB];
__device__ float g_k[(size_t)NTOK * EMB];
__device__ float g_v[(size_t)NTOK * EMB];
__device__ float g_x[(size_t)NTOK * EMB];
__device__ float g_ln[(size_t)NTOK * EMB];
__device__ float g_qi[(size_t)NTOK * EMB];
__device__ float g_ki[(size_t)NTOK * EMB];
__device__ float g_vi[(size_t)NTOK * EMB];
__device__ float g_wq[(size_t)EMB * EMB];
__device__ float g_wk[(size_t)EMB * EMB];
__device__ float g_wv[(size_t)EMB * EMB];
__device__ float g_wo[(size_t)EMB * EMB];

// ---------------- helpers ----------------
__device__ __forceinline__ float tf32f(float x) {
    unsigned u;
    asm("cvt.rna.tf32.f32 %0, %1;" : "=r"(u) : "f"(x));
    return __uint_as_float(u);
}
__device__ __forceinline__ unsigned fbits(float x) { return __float_as_uint(x); }

__device__ __forceinline__ uint32_t smem_u32(const void* p) {
    uint32_t a;
    asm("{ .reg .u64 t; cvta.to.shared.u64 t, %1; cvt.u32.u64 %0, t; }" : "=r"(a) : "l"(p));
    return a;
}

__device__ __forceinline__ void cp16(uint32_t dst, const void* src) {
    asm volatile("cp.async.cg.shared.global [%0], [%1], 16;" :: "r"(dst), "l"(src));
}
#define CP_COMMIT() asm volatile("cp.async.commit_group;" ::: "memory")
#define CP_WAIT1()  asm volatile("cp.async.wait_group 1;" ::: "memory")
#define CP_WAIT0()  asm volatile("cp.async.wait_group 0;" ::: "memory")

__device__ __forceinline__ void ldsm4(unsigned& r0, unsigned& r1, unsigned& r2, unsigned& r3,
                                      uint32_t addr) {
    asm volatile("ldmatrix.sync.aligned.m8n8.x4.shared.b16 {%0,%1,%2,%3}, [%4];"
                 : "=r"(r0), "=r"(r1), "=r"(r2), "=r"(r3) : "r"(addr));
}

__device__ __forceinline__ void mma8(float c[4], const unsigned a[4], const unsigned b[2]) {
    asm volatile(
        "mma.sync.aligned.m16n8k8.row.col.f32.tf32.tf32.f32 "
        "{%0,%1,%2,%3},{%4,%5,%6,%7},{%8,%9},{%0,%1,%2,%3};\n"
        : "+f"(c[0]), "+f"(c[1]), "+f"(c[2]), "+f"(c[3])
        : "r"(a[0]), "r"(a[1]), "r"(a[2]), "r"(a[3]), "r"(b[0]), "r"(b[1]));
}

// ---------------- fused preamble: round inputs/weights (no zero; LN masks) ----
#define SEG4  (NTOK * EMB / 4)
#define WSEG4 (EMB * EMB / 4)
#define PREP_TOTAL4 (3 * SEG4 + 4 * WSEG4)          // 7340032
#define PREP_TTH (PREP_TOTAL4 / 4)                  // 1835008 threads
#define PREP_BLOCKS (PREP_TTH / 256)                // 7168

__global__ void prep_kernel(const float4* __restrict__ q, const float4* __restrict__ k,
                            const float4* __restrict__ v,
                            const float4* __restrict__ wq, const float4* __restrict__ wk,
                            const float4* __restrict__ wv, const float4* __restrict__ wo,
                            float4* __restrict__ qi, float4* __restrict__ ki,
                            float4* __restrict__ vi,
                            float4* __restrict__ owq, float4* __restrict__ owk,
                            float4* __restrict__ owv, float4* __restrict__ owo)
{
    const size_t j = (size_t)blockIdx.x * 256 + threadIdx.x;
#pragma unroll
    for (int rep = 0; rep < 4; rep++) {
        size_t i = j + (size_t)rep * PREP_TTH;
        const float4* src;
        float4* dst;
        if (i < 3 * (size_t)SEG4) {
            size_t s = i / SEG4;
            i -= s * SEG4;
            src = (s == 0) ? q : (s == 1) ? k : v;
            dst = (s == 0) ? qi : (s == 1) ? ki : vi;
        } else {
            i -= 3 * (size_t)SEG4;
            size_t s = i / WSEG4;
            i -= s * WSEG4;
            src = (s == 0) ? wq : (s == 1) ? wk : (s == 2) ? wv : wo;
            dst = (s == 0) ? owq : (s == 1) ? owk : (s == 2) ? owv : owo;
        }
        float4 val = src[i];
        dst[i] = make_float4(tf32f(val.x), tf32f(val.y), tf32f(val.z), tf32f(val.w));
    }
}

// ============================================================================
// GEMM core: operands pre-rounded tf32. CTA 128x128, 8 warps 2x4, warp 64x32,
// KT=32, 3-stage cp.async, 2 CTA/SM. B-fragments via paired ldsm4.
// ============================================================================
#define GKT 32
#define NSTG 3
#define STAGE_FLOATS (2 * 128 * GKT)
#define B_OFF_FLOATS (128 * GKT)
#define GEMM_SMEM_BYTES (NSTG * STAGE_FLOATS * 4)

template <bool RND>
__device__ __forceinline__ void gemm_core(
    const float* __restrict__ A, const float* __restrict__ W,
    const float* __restrict__ bias, float* __restrict__ C,
    float* smf, int bm, int bn)
{
    const uint32_t sb = smem_u32(smf);
    const int tid  = threadIdx.x;
    const int lane = tid & 31;
    const int warp = tid >> 5;
    const int wm_i = warp & 1;
    const int wn_i = warp >> 1;
    const int T = EMB / GKT;   // 32

    auto issue_tile = [&](int t, int buf) {
        const uint32_t base = sb + (uint32_t)buf * (STAGE_FLOATS * 4);
        const float* Ap = A + (size_t)bm * EMB + t * GKT;
        const float* Wp = W + (size_t)bn * EMB + t * GKT;
#pragma unroll
        for (int i = 0; i < 4; i++) {
            int id = tid + i * 256;
            int row = id >> 3;
            int c4 = (id & 7) << 2;
            uint32_t off = (uint32_t)(row * 128 + c4 * 4);
            off ^= (uint32_t)((row & 7) << 4);
            cp16(base + off, Ap + (size_t)row * EMB + c4);
        }
#pragma unroll
        for (int i = 0; i < 4; i++) {
            int id = tid + i * 256;
            int row = id >> 3;
            int c4 = (id & 7) << 2;
            uint32_t off = (uint32_t)(B_OFF_FLOATS * 4 + row * 128 + c4 * 4);
            off ^= (uint32_t)((row & 7) << 4);
            cp16(base + off, Wp + (size_t)row * EMB + c4);
        }
        CP_COMMIT();
    };

    float acc[4][4][4];
#pragma unroll
    for (int mt = 0; mt < 4; mt++)
#pragma unroll
        for (int nt = 0; nt < 4; nt++)
#pragma unroll
            for (int i = 0; i < 4; i++) acc[mt][nt][i] = 0.f;

    issue_tile(0, 0);
    issue_tile(1, 1);

    const int a_rl = ((lane >> 3) & 1) * 8 + (lane & 7);
    const int a_cl = ((lane >> 4) & 1) * 4;
    const int bx_rl = (lane & 7) + (((lane >> 4) & 1) << 3);
    const int bx_cl = ((lane >> 3) & 1) * 4;

    for (int t = 0; t < T; t++) {
        CP_WAIT1();
        __syncthreads();
        if (t + 2 < T) issue_tile(t + 2, (t + 2) % NSTG);
        else CP_COMMIT();

        const uint32_t base  = sb + (uint32_t)(t % NSTG) * (STAGE_FLOATS * 4);
        const uint32_t bbase = base + B_OFF_FLOATS * 4;

#pragma unroll
        for (int kk = 0; kk < 4; kk++) {
            unsigned af[4][4];
#pragma unroll
            for (int mt = 0; mt < 4; mt++) {
                int r = (wm_i * 4 + mt) * 16 + a_rl;
                int cb = kk * 8 + a_cl;
                uint32_t off = (uint32_t)(r * 128 + cb * 4) ^ (uint32_t)((r & 7) << 4);
                ldsm4(af[mt][0], af[mt][1], af[mt][2], af[mt][3], base + off);
            }
            unsigned bf[4][2];
#pragma unroll
            for (int ntp = 0; ntp < 2; ntp++) {
                int n = (wn_i * 4 + ntp * 2) * 8 + bx_rl;
                int cb = kk * 8 + bx_cl;
                uint32_t off = (uint32_t)(n * 128 + cb * 4) ^ (uint32_t)((n & 7) << 4);
                ldsm4(bf[2 * ntp][0], bf[2 * ntp][1], bf[2 * ntp + 1][0], bf[2 * ntp + 1][1],
                      bbase + off);
            }
#pragma unroll
            for (int mt = 0; mt < 4; mt++)
#pragma unroll
                for (int nt = 0; nt < 4; nt++)
                    mma8(acc[mt][nt], af[mt], bf[nt]);
        }
    }

    const int l3 = lane & 3;
    const int lr = lane >> 2;
#pragma unroll
    for (int mt = 0; mt < 4; mt++) {
        int r0 = bm + wm_i * 64 + mt * 16 + lr;
#pragma unroll
        for (int nt = 0; nt < 4; nt++) {
            int c = bn + wn_i * 32 + nt * 8 + l3 * 2;
            float b0 = __ldg(bias + c), b1 = __ldg(bias + c + 1);
            float v00 = acc[mt][nt][0] + b0, v01 = acc[mt][nt][1] + b1;
            float v10 = acc[mt][nt][2] + b0, v11 = acc[mt][nt][3] + b1;
            if (RND) { v00 = tf32f(v00); v01 = tf32f(v01); v10 = tf32f(v10); v11 = tf32f(v11); }
            *(float2*)(C + (size_t)r0 * EMB + c)       = make_float2(v00, v01);
            *(float2*)(C + (size_t)(r0 + 8) * EMB + c) = make_float2(v10, v11);
        }
    }
}

__global__ __launch_bounds__(256, 2) void qkv_gemm_kernel(
    const float* A0, const float* A1, const float* A2,
    const float* W0, const float* W1, const float* W2,
    const float* b0, const float* b1, const float* b2,
    float* C0, float* C1, float* C2)
{
    extern __shared__ float smf[];
    const int z = blockIdx.z;
    const float* A = (z == 0) ? A0 : (z == 1) ? A1 : A2;
    const float* W = (z == 0) ? W0 : (z == 1) ? W1 : W2;
    const float* bias = (z == 0) ? b0 : (z == 1) ? b1 : b2;
    float* C = (z == 0) ? C0 : (z == 1) ? C1 : C2;
    gemm_core<true>(A, W, bias, C, smf, blockIdx.y * 128, blockIdx.x * 128);
}

__global__ __launch_bounds__(256, 2) void out_gemm_kernel(
    const float* __restrict__ A, const float* __restrict__ W,
    const float* __restrict__ bias, float* __restrict__ C)
{
    extern __shared__ float smf[];
    gemm_core<false>(A, W, bias, C, smf, blockIdx.y * 128, blockIdx.x * 128);
}

// ============================================================================
// Attention (R15, unchanged): j-block 64 double-buffered, register-resident S,
// paired ldsm4 K-fragments.
// ============================================================================
#define AQP 68
#define AKP 68
#define AVP 72
#define KBUF_B (64 * AKP * 4)
#define VBUF_B (64 * AVP * 4)
#define Q_B    (128 * AQP * 4)
#define ATTN_SMEM_BYTES (Q_B + 2 * KBUF_B + 2 * VBUF_B)   // 104 KB

__global__ __launch_bounds__(256, 2) void attn_kernel() {
    extern __shared__ float sm[];
    const uint32_t sb = smem_u32(sm);
    const uint32_t kb0 = sb + Q_B;
    const uint32_t vb0 = sb + Q_B + 2 * KBUF_B;

    const int p = blockIdx.y;
    int rate, off, head, segbase;
    if (p < 24)      { rate = 1; off = 0; segbase = (p / 6) * 2048;         head = p % 6; }
    else if (p < 34) { int q = p - 24; rate = 2; off = 1; segbase = (q / 5) * 4096; head = 6 + q % 5; }
    else             { int q = p - 34; rate = 4; off = 2; segbase = 0;             head = 11 + q; }

    const int tid = threadIdx.x;
    const int lane = tid & 31;
    const int warp = tid >> 5;
    const int l3 = lane & 3;
    const int lr = lane >> 2;
    const int q0 = blockIdx.x * 128;
    const float scale = 0.125f;

    for (int i = tid; i < 2048; i += 256) {
        int s = i >> 4;
        int c4 = (i & 15) << 2;
        int tok = segbase + off + (q0 + s) * rate;
        const float4 v = *(const float4*)(g_q + ((size_t)tok * NH + head) * HD + c4);
        float* d = sm + s * AQP + c4;
        d[0] = v.x * scale; d[1] = v.y * scale;
        d[2] = v.z * scale; d[3] = v.w * scale;
    }

    auto issue_kv = [&](int t, int buf) {
        const uint32_t kd = kb0 + (uint32_t)buf * KBUF_B;
        const uint32_t vd = vb0 + (uint32_t)buf * VBUF_B;
#pragma unroll
        for (int i = 0; i < 4; i++) {
            int id = tid + i * 256;
            int row = id >> 4;
            int cf = (id & 15) << 2;
            int tok = segbase + off + (t * 64 + row) * rate;
            cp16(kd + (uint32_t)((row * AKP + cf) * 4),
                 g_k + ((size_t)tok * NH + head) * HD + cf);
        }
#pragma unroll
        for (int i = 0; i < 4; i++) {
            int id = tid + i * 256;
            int row = id >> 4;
            int cf = (id & 15) << 2;
            int tok = segbase + off + (t * 64 + row) * rate;
            cp16(vd + (uint32_t)((row * AVP + cf) * 4),
                 g_v + ((size_t)tok * NH + head) * HD + cf);
        }
        CP_COMMIT();
    };

    const int a_rl = ((lane >> 3) & 1) * 8 + (lane & 7);
    const int a_cl = ((lane >> 4) & 1) * 4;
    const int bx_rl = (lane & 7) + (((lane >> 4) & 1) << 3);
    const int bx_cl = ((lane >> 3) & 1) * 4;
    const int srcA = (lane & ~3) | (l3 >> 1);
    const int srcB = srcA + 2;
    const bool odd = (l3 & 1);

    float o[8][4];
#pragma unroll
    for (int nt = 0; nt < 8; nt++) { o[nt][0] = o[nt][1] = o[nt][2] = o[nt][3] = 0.f; }
    float m0 = -1e30f, m1 = -1e30f, l0 = 0.f, l1 = 0.f;

    issue_kv(0, 0);

    const int T = 2048 / 64;
    for (int t = 0; t < T; t++) {
        if (t + 1 < T) { issue_kv(t + 1, (t + 1) & 1); CP_WAIT1(); }
        else           { CP_WAIT0(); }
        __syncthreads();

        const uint32_t kd = kb0 + (uint32_t)(t & 1) * KBUF_B;
        const float* Vsb = sm + (Q_B + 2 * KBUF_B + (t & 1) * VBUF_B) / 4;

        float s[8][4];
#pragma unroll
        for (int nt = 0; nt < 8; nt++) { s[nt][0] = s[nt][1] = s[nt][2] = s[nt][3] = 0.f; }
#pragma unroll
        for (int kk = 0; kk < 8; kk++) {
            unsigned qa[4];
            {
                int r = warp * 16 + a_rl;
                ldsm4(qa[0], qa[1], qa[2], qa[3],
                      sb + (uint32_t)((r * AQP + kk * 8 + a_cl) * 4));
            }
            unsigned kb[8][2];
#pragma unroll
            for (int ntp = 0; ntp < 4; ntp++) {
                int n = ntp * 16 + bx_rl;
                ldsm4(kb[2 * ntp][0], kb[2 * ntp][1], kb[2 * ntp + 1][0], kb[2 * ntp + 1][1],
                      kd + (uint32_t)((n * AKP + kk * 8 + bx_cl) * 4));
            }
#pragma unroll
            for (int nt = 0; nt < 8; nt++)
                mma8(s[nt], qa, kb[nt]);
        }
        float mx0 = -1e30f, mx1 = -1e30f;
#pragma unroll
        for (int nt = 0; nt < 8; nt++) {
            mx0 = fmaxf(mx0, fmaxf(s[nt][0], s[nt][1]));
            mx1 = fmaxf(mx1, fmaxf(s[nt][2], s[nt][3]));
        }
        mx0 = fmaxf(mx0, __shfl_xor_sync(0xffffffffu, mx0, 1));
        mx0 = fmaxf(mx0, __shfl_xor_sync(0xffffffffu, mx0, 2));
        mx1 = fmaxf(mx1, __shfl_xor_sync(0xffffffffu, mx1, 1));
        mx1 = fmaxf(mx1, __shfl_xor_sync(0xffffffffu, mx1, 2));
        float mn0 = fmaxf(m0, mx0), mn1 = fmaxf(m1, mx1);
        float al0 = __expf(m0 - mn0), al1 = __expf(m1 - mn1);
#pragma unroll
        for (int nt = 0; nt < 8; nt++) {
            o[nt][0] *= al0; o[nt][1] *= al0; o[nt][2] *= al1; o[nt][3] *= al1;
        }
        float sum0 = 0.f, sum1 = 0.f;
#pragma unroll
        for (int nt = 0; nt < 8; nt++) {
            float e0 = __expf(s[nt][0] - mn0); sum0 += e0; s[nt][0] = tf32f(e0);
            float e1 = __expf(s[nt][1] - mn0); sum0 += e1; s[nt][1] = tf32f(e1);
            float e2 = __expf(s[nt][2] - mn1); sum1 += e2; s[nt][2] = tf32f(e2);
            float e3 = __expf(s[nt][3] - mn1); sum1 += e3; s[nt][3] = tf32f(e3);
        }
        sum0 += __shfl_xor_sync(0xffffffffu, sum0, 1);
        sum0 += __shfl_xor_sync(0xffffffffu, sum0, 2);
        sum1 += __shfl_xor_sync(0xffffffffu, sum1, 1);
        sum1 += __shfl_xor_sync(0xffffffffu, sum1, 2);
        l0 = l0 * al0 + sum0;
        l1 = l1 * al1 + sum1;
        m0 = mn0; m1 = mn1;

#pragma unroll
        for (int kk = 0; kk < 8; kk++) {
            unsigned a[4];
            {
                float u, v;
                u = __shfl_sync(0xffffffffu, s[kk][0], srcA);
                v = __shfl_sync(0xffffffffu, s[kk][1], srcA);
                a[0] = fbits(odd ? v : u);
                u = __shfl_sync(0xffffffffu, s[kk][2], srcA);
                v = __shfl_sync(0xffffffffu, s[kk][3], srcA);
                a[1] = fbits(odd ? v : u);
                u = __shfl_sync(0xffffffffu, s[kk][0], srcB);
                v = __shfl_sync(0xffffffffu, s[kk][1], srcB);
                a[2] = fbits(odd ? v : u);
                u = __shfl_sync(0xffffffffu, s[kk][2], srcB);
                v = __shfl_sync(0xffffffffu, s[kk][3], srcB);
                a[3] = fbits(odd ? v : u);
            }
            const int kr = kk * 8 + l3;
#pragma unroll
            for (int nto = 0; nto < 8; nto++) {
                unsigned b[2];
                b[0] = fbits(Vsb[kr * AVP + nto * 8 + lr]);
                b[1] = fbits(Vsb[(kr + 4) * AVP + nto * 8 + lr]);
                mma8(o[nto], a, b);
            }
        }
        __syncthreads();
    }

    {
        float inv0 = 1.f / l0;
        float inv1 = 1.f / l1;
        int tok0 = segbase + off + (q0 + warp * 16 + lr) * rate;
        int tok1 = segbase + off + (q0 + warp * 16 + lr + 8) * rate;
#pragma unroll
        for (int nt = 0; nt < 8; nt++) {
            int c = nt * 8 + (l3 << 1);
            *(float2*)(g_x + ((size_t)tok0 * NH + head) * HD + c) =
                make_float2(o[nt][0] * inv0, o[nt][1] * inv0);
            *(float2*)(g_x + ((size_t)tok1 * NH + head) * HD + c) =
                make_float2(o[nt][2] * inv1, o[nt][3] * inv1);
        }
    }
}

// ---------------- LayerNorm: masks uncovered (token, head) slots to 0 ----------
__global__ __launch_bounds__(256) void ln_kernel(
    const float* __restrict__ x_in, float* __restrict__ y_out,
    const float* __restrict__ gam, const float* __restrict__ bet)
{
    __shared__ float red[16];
    const int row = blockIdx.x;
    const int tid = threadIdx.x;
    const int c = tid * 4;
    const int h = c >> 6;
    // coverage: heads 0-5 all tokens; 6-10 tokens t%2==1; 11-15 tokens t%4==2
    const bool covered = (h < 6) || (h < 11 ? ((row & 1) == 1) : ((row & 3) == 2));
    float4 xv = *(const float4*)(x_in + (size_t)row * EMB + c);
    if (!covered) xv = make_float4(0.f, 0.f, 0.f, 0.f);
    float s = xv.x + xv.y + xv.z + xv.w;
    float s2 = xv.x * xv.x + xv.y * xv.y + xv.z * xv.z + xv.w * xv.w;
#pragma unroll
    for (int o = 16; o; o >>= 1) {
        s += __shfl_xor_sync(0xffffffffu, s, o);
        s2 += __shfl_xor_sync(0xffffffffu, s2, o);
    }
    if ((tid & 31) == 0) { red[tid >> 5] = s; red[8 + (tid >> 5)] = s2; }
    __syncthreads();
    if (tid < 32) {
        float a = (tid < 8) ? red[tid] : 0.f;
        float b = (tid < 8) ? red[8 + tid] : 0.f;
#pragma unroll
        for (int o = 4; o; o >>= 1) {
            a += __shfl_xor_sync(0xffffffffu, a, o);
            b += __shfl_xor_sync(0xffffffffu, b, o);
        }
        if (tid == 0) { red[0] = a; red[1] = b; }
    }
    __syncthreads();
    const float mu = red[0] * (1.f / EMB);
    const float var = red[1] * (1.f / EMB) - mu * mu;
    const float rs = rsqrtf(var + 1e-5f);
    const float4 gv = *(const float4*)(gam + c);
    const float4 bv = *(const float4*)(bet + c);
    float4 ov;
    ov.x = tf32f((xv.x - mu) * rs * gv.x + bv.x);
    ov.y = tf32f((xv.y - mu) * rs * gv.y + bv.y);
    ov.z = tf32f((xv.z - mu) * rs * gv.z + bv.z);
    ov.w = tf32f((xv.w - mu) * rs * gv.w + bv.w);
    *(float4*)(y_out + (size_t)row * EMB + c) = ov;
}

// ---------------- launch ----------------
extern "C" void kernel_launch(void* const* d_in, const int* in_sizes, int n_in,
                              void* d_out, int out_size)
{
    (void)in_sizes; (void)n_in; (void)out_size;
    const float* query = (const float*)d_in[0];
    const float* key   = (const float*)d_in[1];
    const float* value = (const float*)d_in[2];
    const float* Wq = (const float*)d_in[3];
    const float* bq = (const float*)d_in[4];
    const float* Wk = (const float*)d_in[5];
    const float* bk = (const float*)d_in[6];
    const float* Wv = (const float*)d_in[7];
    const float* bv = (const float*)d_in[8];
    const float* Wo = (const float*)d_in[9];
    const float* bo = (const float*)d_in[10];
    const float* ln_g = (const float*)d_in[11];
    const float* ln_b = (const float*)d_in[12];
    float* out = (float*)d_out;

    float *pq, *pk, *pv, *px, *pln, *pqi, *pki, *pvi, *pwq, *pwk, *pwv, *pwo;
    cudaGetSymbolAddress((void**)&pq, g_q);
    cudaGetSymbolAddress((void**)&pk, g_k);
    cudaGetSymbolAddress((void**)&pv, g_v);
    cudaGetSymbolAddress((void**)&px, g_x);
    cudaGetSymbolAddress((void**)&pln, g_ln);
    cudaGetSymbolAddress((void**)&pqi, g_qi);
    cudaGetSymbolAddress((void**)&pki, g_ki);
    cudaGetSymbolAddress((void**)&pvi, g_vi);
    cudaGetSymbolAddress((void**)&pwq, g_wq);
    cudaGetSymbolAddress((void**)&pwk, g_wk);
    cudaGetSymbolAddress((void**)&pwv, g_wv);
    cudaGetSymbolAddress((void**)&pwo, g_wo);

    prep_kernel<<<PREP_BLOCKS, 256>>>(
        (const float4*)query, (const float4*)key, (const float4*)value,
        (const float4*)Wq, (const float4*)Wk, (const float4*)Wv, (const float4*)Wo,
        (float4*)pqi, (float4*)pki, (float4*)pvi,
        (float4*)pwq, (float4*)pwk, (float4*)pwv, (float4*)pwo);

    cudaFuncSetAttribute(qkv_gemm_kernel,
                         cudaFuncAttributeMaxDynamicSharedMemorySize, GEMM_SMEM_BYTES);
    cudaFuncSetAttribute(out_gemm_kernel,
                         cudaFuncAttributeMaxDynamicSharedMemorySize, GEMM_SMEM_BYTES);

    qkv_gemm_kernel<<<dim3(EMB / 128, NTOK / 128, 3), 256, GEMM_SMEM_BYTES>>>(
        pqi, pki, pvi, pwq, pwk, pwv, bq, bk, bv, pq, pk, pv);

    cudaFuncSetAttribute(attn_kernel, cudaFuncAttributeMaxDynamicSharedMemorySize,
                         ATTN_SMEM_BYTES);
    attn_kernel<<<dim3(16, 39), 256, ATTN_SMEM_BYTES>>>();

    ln_kernel<<<NTOK, 256>>>(px, pln, ln_g, ln_b);

    out_gemm_kernel<<<dim3(EMB / 128, NTOK / 128), 256, GEMM_SMEM_BYTES>>>(
        pln, pwo, bo, out);
}